// round 7
// baseline (speedup 1.0000x reference)
#include <cuda_runtime.h>
#include <cstdint>
#include <math.h>

// Problem constants
#define BATCH 4
#define SEQ   2048
#define DIM   1024
#define HEADS 16
#define DHEAD 64
#define MTOT  (BATCH * SEQ)   // 8192

// ---------------------------------------------------------------------------
// Scratch (no cudaMalloc allowed)
// ---------------------------------------------------------------------------
__device__ float g_qh[(size_t)MTOT * DIM];
__device__ float g_kh[(size_t)MTOT * DIM];
__device__ float g_vh[(size_t)MTOT * DIM];
__device__ float g_ao[(size_t)MTOT * DIM];

// ---------------------------------------------------------------------------
// tf32 helpers
// ---------------------------------------------------------------------------
__device__ __forceinline__ uint32_t cvt_tf32(float f) {
    uint32_t u;
    asm("cvt.rna.tf32.f32 %0, %1;" : "=r"(u) : "f"(f));
    return u;
}

__device__ __forceinline__ void mma_tf32(float c[4], const uint32_t a[4], const uint32_t b[2]) {
    asm volatile(
        "mma.sync.aligned.m16n8k8.row.col.f32.tf32.tf32.f32 "
        "{%0,%1,%2,%3}, {%4,%5,%6,%7}, {%8,%9}, {%0,%1,%2,%3};"
        : "+f"(c[0]), "+f"(c[1]), "+f"(c[2]), "+f"(c[3])
        : "r"(a[0]), "r"(a[1]), "r"(a[2]), "r"(a[3]),
          "r"(b[0]), "r"(b[1]));
}

__device__ __forceinline__ void cp16(uint32_t dst, const float* src) {
    asm volatile("cp.async.cg.shared.global [%0], [%1], 16;" :: "r"(dst), "l"(src));
}

// ---------------------------------------------------------------------------
// Generic GEMM: C[M][N] = alpha * A[M][K] * Bw[N][K]^T  (row-major fp32)
// CTA tile 128x128, K-step 16, 256 threads (8 warps 2x4), warp tile 64x32.
// ---------------------------------------------------------------------------
#define GM_PAD 20

__global__ __launch_bounds__(256) void gemm_tf32_kernel(
    const float* __restrict__ A, const float* __restrict__ Bw,
    float* __restrict__ C, int M, int N, int K, float alpha)
{
    __shared__ uint32_t sA[2][128 * GM_PAD];
    __shared__ uint32_t sB[2][128 * GM_PAD];

    const int tid  = threadIdx.x;
    const int m0   = blockIdx.y * 128;
    const int n0   = blockIdx.x * 128;
    const int lane = tid & 31, wid = tid >> 5;
    const int wr   = wid >> 2;
    const int wc   = wid & 3;
    const int gid  = lane >> 2, tig = lane & 3;

    float acc[4][4][4];
#pragma unroll
    for (int mt = 0; mt < 4; mt++)
#pragma unroll
        for (int nt = 0; nt < 4; nt++)
#pragma unroll
            for (int r = 0; r < 4; r++) acc[mt][nt][r] = 0.f;

    float4 ra[2], rb[2];

#pragma unroll
    for (int i = 0; i < 2; i++) {
        int f = tid + i * 256, row = f >> 2, c4 = (f & 3) * 4;
        ra[i] = *reinterpret_cast<const float4*>(A  + (size_t)(m0 + row) * K + c4);
        rb[i] = *reinterpret_cast<const float4*>(Bw + (size_t)(n0 + row) * K + c4);
    }
#pragma unroll
    for (int i = 0; i < 2; i++) {
        int f = tid + i * 256, row = f >> 2, c4 = (f & 3) * 4;
        uint32_t* pa = &sA[0][row * GM_PAD + c4];
        pa[0] = cvt_tf32(ra[i].x); pa[1] = cvt_tf32(ra[i].y);
        pa[2] = cvt_tf32(ra[i].z); pa[3] = cvt_tf32(ra[i].w);
        uint32_t* pb = &sB[0][row * GM_PAD + c4];
        pb[0] = cvt_tf32(rb[i].x); pb[1] = cvt_tf32(rb[i].y);
        pb[2] = cvt_tf32(rb[i].z); pb[3] = cvt_tf32(rb[i].w);
    }
    __syncthreads();

    const int NIT = K / 16;
    for (int it = 0; it < NIT; ++it) {
        const int cur = it & 1;
        if (it + 1 < NIT) {
            const int k0 = (it + 1) * 16;
#pragma unroll
            for (int i = 0; i < 2; i++) {
                int f = tid + i * 256, row = f >> 2, c4 = (f & 3) * 4;
                ra[i] = *reinterpret_cast<const float4*>(A  + (size_t)(m0 + row) * K + k0 + c4);
                rb[i] = *reinterpret_cast<const float4*>(Bw + (size_t)(n0 + row) * K + k0 + c4);
            }
        }
#pragma unroll
        for (int kk = 0; kk < 16; kk += 8) {
            uint32_t af[4][4], bf[4][2];
#pragma unroll
            for (int mt = 0; mt < 4; mt++) {
                const int r = wr * 64 + mt * 16;
                af[mt][0] = sA[cur][(r + gid)     * GM_PAD + kk + tig];
                af[mt][1] = sA[cur][(r + gid + 8) * GM_PAD + kk + tig];
                af[mt][2] = sA[cur][(r + gid)     * GM_PAD + kk + tig + 4];
                af[mt][3] = sA[cur][(r + gid + 8) * GM_PAD + kk + tig + 4];
            }
#pragma unroll
            for (int nt = 0; nt < 4; nt++) {
                const int c = wc * 32 + nt * 8;
                bf[nt][0] = sB[cur][(c + gid) * GM_PAD + kk + tig];
                bf[nt][1] = sB[cur][(c + gid) * GM_PAD + kk + tig + 4];
            }
#pragma unroll
            for (int mt = 0; mt < 4; mt++)
#pragma unroll
                for (int nt = 0; nt < 4; nt++)
                    mma_tf32(acc[mt][nt], af[mt], bf[nt]);
        }
        if (it + 1 < NIT) {
            const int nxt = cur ^ 1;
#pragma unroll
            for (int i = 0; i < 2; i++) {
                int f = tid + i * 256, row = f >> 2, c4 = (f & 3) * 4;
                uint32_t* pa = &sA[nxt][row * GM_PAD + c4];
                pa[0] = cvt_tf32(ra[i].x); pa[1] = cvt_tf32(ra[i].y);
                pa[2] = cvt_tf32(ra[i].z); pa[3] = cvt_tf32(ra[i].w);
                uint32_t* pb = &sB[nxt][row * GM_PAD + c4];
                pb[0] = cvt_tf32(rb[i].x); pb[1] = cvt_tf32(rb[i].y);
                pb[2] = cvt_tf32(rb[i].z); pb[3] = cvt_tf32(rb[i].w);
            }
        }
        __syncthreads();
    }

#pragma unroll
    for (int mt = 0; mt < 4; mt++) {
        const int r = m0 + wr * 64 + mt * 16 + gid;
#pragma unroll
        for (int nt = 0; nt < 4; nt++) {
            const int c = n0 + wc * 32 + nt * 8 + tig * 2;
            float2 v0 = make_float2(alpha * acc[mt][nt][0], alpha * acc[mt][nt][1]);
            float2 v1 = make_float2(alpha * acc[mt][nt][2], alpha * acc[mt][nt][3]);
            *reinterpret_cast<float2*>(C + (size_t)r * N + c)       = v0;
            *reinterpret_cast<float2*>(C + (size_t)(r + 8) * N + c) = v1;
        }
    }
}

// ---------------------------------------------------------------------------
// Flash attention v4 (max-free softmax, tf32) — sized for 2 CTAs/SM.
// CTA = 128 q-rows; j-chunks of 32; 256 threads; warp grid 4x2.
// S stage:  warp tile 32 rows x 16 j-cols (nt=2).
// PV stage: warp tile 32 rows x 32 d-cols (nt=4).
// K/V: cp.async double-buffered raw fp32 (cvt->tf32 at frag load).
// smem = 90 KB, regs capped 128 via __launch_bounds__(256,2).
// ---------------------------------------------------------------------------
#define CHUNK 32
#define FA_QS 68
#define FA_PS 36
#define FA_KS 68
#define FA_VS 72
#define OFF_Q 0
#define OFF_P (128 * FA_QS)                  // 8704
#define OFF_K (OFF_P + 128 * FA_PS)          // 13312
#define OFF_V (OFF_K + 2 * CHUNK * FA_KS)    // 17664
#define OFF_L (OFF_V + 2 * CHUNK * FA_VS)    // 22272
#define FA_WORDS (OFF_L + 256)               // 22528
#define FA_SMEM_BYTES (FA_WORDS * 4)         // 90112 B

__global__ __launch_bounds__(256, 2) void flash_attn_kernel(const float* __restrict__ bias)
{
    extern __shared__ uint32_t sm[];
    uint32_t* qsm  = sm + OFF_Q;
    uint32_t* psmu = sm + OFF_P;
    float*    lred = reinterpret_cast<float*>(sm + OFF_L);
    const uint32_t smem_u32 = (uint32_t)__cvta_generic_to_shared(sm);

    const int tid  = threadIdx.x;
    const int i0   = blockIdx.x * 128;
    const int h    = blockIdx.y;
    const int b    = blockIdx.z;
    const int lane = tid & 31, wid = tid >> 5;
    const int wr   = wid >> 1;   // 0..3 -> 32-row group
    const int wc   = wid & 1;    // 0..1
    const int gid  = lane >> 2, tig = lane & 3;

    // load q tile (128 rows x 64) -> tf32 smem
    const float* qbase = g_qh + ((size_t)(b * SEQ + i0)) * DIM + h * DHEAD;
#pragma unroll
    for (int i = 0; i < 8; i++) {
        int f = tid + i * 256, row = f >> 4, c4 = (f & 15) * 4;
        float4 v = *reinterpret_cast<const float4*>(qbase + (size_t)row * DIM + c4);
        uint32_t* p = &qsm[row * FA_QS + c4];
        *reinterpret_cast<uint2*>(p)     = make_uint2(cvt_tf32(v.x), cvt_tf32(v.y));
        *reinterpret_cast<uint2*>(p + 2) = make_uint2(cvt_tf32(v.z), cvt_tf32(v.w));
    }

    float oacc[2][4][4];
#pragma unroll
    for (int mt = 0; mt < 2; mt++)
#pragma unroll
        for (int nt = 0; nt < 4; nt++)
#pragma unroll
            for (int r = 0; r < 4; r++) oacc[mt][nt][r] = 0.f;

    float lacc[4] = {0.f, 0.f, 0.f, 0.f};

    const float* biasbase = bias + ((size_t)h * SEQ + i0) * SEQ;
    const float* kroot = g_kh + ((size_t)(b * SEQ)) * DIM + h * DHEAD;
    const float* vroot = g_vh + ((size_t)(b * SEQ)) * DIM + h * DHEAD;

    // issue chunk 0 (32 rows x 64 cols, K and V)
    {
        const uint32_t kdst = smem_u32 + OFF_K * 4;
        const uint32_t vdst = smem_u32 + OFF_V * 4;
#pragma unroll
        for (int i = 0; i < 2; i++) {
            int idx = tid + i * 256, row = idx >> 4, c16 = (idx & 15) * 4;
            cp16(kdst + (row * FA_KS + c16) * 4, kroot + (size_t)row * DIM + c16);
            cp16(vdst + (row * FA_VS + c16) * 4, vroot + (size_t)row * DIM + c16);
        }
        asm volatile("cp.async.commit_group;");
    }

    const int NC = SEQ / CHUNK;
    for (int jc = 0; jc < NC; ++jc) {
        const int j0  = jc * CHUNK;
        const int cur = jc & 1;
        const float* kbuf = reinterpret_cast<const float*>(sm + OFF_K + cur * CHUNK * FA_KS);
        const float* vbuf = reinterpret_cast<const float*>(sm + OFF_V + cur * CHUNK * FA_VS);

        // issue next chunk into other buffer
        if (jc + 1 < NC) {
            const int nb = cur ^ 1;
            const uint32_t kdst = smem_u32 + (OFF_K + nb * CHUNK * FA_KS) * 4;
            const uint32_t vdst = smem_u32 + (OFF_V + nb * CHUNK * FA_VS) * 4;
            const float* kb = kroot + (size_t)(j0 + CHUNK) * DIM;
            const float* vb = vroot + (size_t)(j0 + CHUNK) * DIM;
#pragma unroll
            for (int i = 0; i < 2; i++) {
                int idx = tid + i * 256, row = idx >> 4, c16 = (idx & 15) * 4;
                cp16(kdst + (row * FA_KS + c16) * 4, kb + (size_t)row * DIM + c16);
                cp16(vdst + (row * FA_VS + c16) * 4, vb + (size_t)row * DIM + c16);
            }
            asm volatile("cp.async.commit_group;");
            asm volatile("cp.async.wait_group 1;");
        } else {
            asm volatile("cp.async.wait_group 0;");
        }
        __syncthreads();

        // bias fragments (8 floats, prefetched before S MMA)
        float2 bfr[2][2][2];
#pragma unroll
        for (int mt = 0; mt < 2; mt++) {
            const int r = wr * 32 + mt * 16 + gid;
#pragma unroll
            for (int nt = 0; nt < 2; nt++) {
                const int c = wc * 16 + nt * 8 + tig * 2;
                bfr[mt][nt][0] = *reinterpret_cast<const float2*>(biasbase + (size_t)r * SEQ + j0 + c);
                bfr[mt][nt][1] = *reinterpret_cast<const float2*>(biasbase + (size_t)(r + 8) * SEQ + j0 + c);
            }
        }

        // S = q * k^T   (k-dim 64, n-dim 32 -> per warp 16 cols, nt=2)
        float sacc[2][2][4];
#pragma unroll
        for (int mt = 0; mt < 2; mt++)
#pragma unroll
            for (int nt = 0; nt < 2; nt++)
#pragma unroll
                for (int r = 0; r < 4; r++) sacc[mt][nt][r] = 0.f;

#pragma unroll
        for (int kk = 0; kk < 64; kk += 8) {
            uint32_t af[2][4], bf2[2][2];
#pragma unroll
            for (int mt = 0; mt < 2; mt++) {
                const int r = wr * 32 + mt * 16;
                af[mt][0] = qsm[(r + gid)     * FA_QS + kk + tig];
                af[mt][1] = qsm[(r + gid + 8) * FA_QS + kk + tig];
                af[mt][2] = qsm[(r + gid)     * FA_QS + kk + tig + 4];
                af[mt][3] = qsm[(r + gid + 8) * FA_QS + kk + tig + 4];
            }
#pragma unroll
            for (int nt = 0; nt < 2; nt++) {
                const int c = wc * 16 + nt * 8;
                bf2[nt][0] = cvt_tf32(kbuf[(c + gid) * FA_KS + kk + tig]);
                bf2[nt][1] = cvt_tf32(kbuf[(c + gid) * FA_KS + kk + tig + 4]);
            }
#pragma unroll
            for (int mt = 0; mt < 2; mt++)
#pragma unroll
                for (int nt = 0; nt < 2; nt++)
                    mma_tf32(sacc[mt][nt], af[mt], bf2[nt]);
        }

        // p = exp(s + bias); accumulate row sums; store tf32 P (stride 36)
#pragma unroll
        for (int mt = 0; mt < 2; mt++) {
            const int r = wr * 32 + mt * 16 + gid;
#pragma unroll
            for (int nt = 0; nt < 2; nt++) {
                const int c = wc * 16 + nt * 8 + tig * 2;
                float p0 = __expf(sacc[mt][nt][0] + bfr[mt][nt][0].x);
                float p1 = __expf(sacc[mt][nt][1] + bfr[mt][nt][0].y);
                float p2 = __expf(sacc[mt][nt][2] + bfr[mt][nt][1].x);
                float p3 = __expf(sacc[mt][nt][3] + bfr[mt][nt][1].y);
                lacc[mt * 2 + 0] += p0 + p1;
                lacc[mt * 2 + 1] += p2 + p3;
                *reinterpret_cast<uint2*>(&psmu[r * FA_PS + c]) =
                    make_uint2(cvt_tf32(p0), cvt_tf32(p1));
                *reinterpret_cast<uint2*>(&psmu[(r + 8) * FA_PS + c]) =
                    make_uint2(cvt_tf32(p2), cvt_tf32(p3));
            }
        }
        __syncthreads();

        // O += P * V   (k-dim 32, n-dim 64 -> per warp 32 d-cols, nt=4)
#pragma unroll
        for (int kk = 0; kk < CHUNK; kk += 8) {
            uint32_t af[2][4], bf2[4][2];
#pragma unroll
            for (int mt = 0; mt < 2; mt++) {
                const int r = wr * 32 + mt * 16;
                af[mt][0] = psmu[(r + gid)     * FA_PS + kk + tig];
                af[mt][1] = psmu[(r + gid + 8) * FA_PS + kk + tig];
                af[mt][2] = psmu[(r + gid)     * FA_PS + kk + tig + 4];
                af[mt][3] = psmu[(r + gid + 8) * FA_PS + kk + tig + 4];
            }
#pragma unroll
            for (int nt = 0; nt < 4; nt++) {
                const int c = wc * 32 + nt * 8;
                bf2[nt][0] = cvt_tf32(vbuf[(kk + tig)     * FA_VS + c + gid]);
                bf2[nt][1] = cvt_tf32(vbuf[(kk + tig + 4) * FA_VS + c + gid]);
            }
#pragma unroll
            for (int mt = 0; mt < 2; mt++)
#pragma unroll
                for (int nt = 0; nt < 4; nt++)
                    mma_tf32(oacc[mt][nt], af[mt], bf2[nt]);
        }
        __syncthreads();
    }

    // final row-sum reduction: quad shfl then across the 2 column-warps
#pragma unroll
    for (int i = 0; i < 4; i++) {
        lacc[i] += __shfl_xor_sync(0xffffffffu, lacc[i], 1);
        lacc[i] += __shfl_xor_sync(0xffffffffu, lacc[i], 2);
    }
    if (tig == 0) {
#pragma unroll
        for (int mt = 0; mt < 2; mt++) {
            lred[wc * 128 + wr * 32 + mt * 16 + gid]     = lacc[mt * 2 + 0];
            lred[wc * 128 + wr * 32 + mt * 16 + gid + 8] = lacc[mt * 2 + 1];
        }
    }
    __syncthreads();

    float inv[4];
#pragma unroll
    for (int mt = 0; mt < 2; mt++) {
        const int r0 = wr * 32 + mt * 16 + gid;
        inv[mt * 2 + 0] = 1.f / (lred[r0] + lred[128 + r0]);
        const int r1 = r0 + 8;
        inv[mt * 2 + 1] = 1.f / (lred[r1] + lred[128 + r1]);
    }

    float* obase = g_ao + ((size_t)(b * SEQ + i0)) * DIM + h * DHEAD;
#pragma unroll
    for (int mt = 0; mt < 2; mt++) {
        const int r = wr * 32 + mt * 16 + gid;
        const float inv0 = inv[mt * 2 + 0];
        const float inv1 = inv[mt * 2 + 1];
#pragma unroll
        for (int nt = 0; nt < 4; nt++) {
            const int c = wc * 32 + nt * 8 + tig * 2;
            *reinterpret_cast<float2*>(obase + (size_t)r * DIM + c) =
                make_float2(oacc[mt][nt][0] * inv0, oacc[mt][nt][1] * inv0);
            *reinterpret_cast<float2*>(obase + (size_t)(r + 8) * DIM + c) =
                make_float2(oacc[mt][nt][2] * inv1, oacc[mt][nt][3] * inv1);
        }
    }
}

// ---------------------------------------------------------------------------
// launch
// ---------------------------------------------------------------------------
extern "C" void kernel_launch(void* const* d_in, const int* in_sizes, int n_in,
                              void* d_out, int out_size)
{
    (void)in_sizes; (void)n_in; (void)out_size;
    const float* q    = (const float*)d_in[0];
    const float* k    = (const float*)d_in[1];
    const float* v    = (const float*)d_in[2];
    const float* bias = (const float*)d_in[3];
    const float* Wq   = (const float*)d_in[4];
    const float* Wk   = (const float*)d_in[5];
    const float* Wv   = (const float*)d_in[6];
    const float* Wo   = (const float*)d_in[7];
    float* out        = (float*)d_out;

    float *qh, *kh, *vh, *ao;
    cudaGetSymbolAddress((void**)&qh, g_qh);
    cudaGetSymbolAddress((void**)&kh, g_kh);
    cudaGetSymbolAddress((void**)&vh, g_vh);
    cudaGetSymbolAddress((void**)&ao, g_ao);

    cudaFuncSetAttribute(flash_attn_kernel,
                         cudaFuncAttributeMaxDynamicSharedMemorySize, FA_SMEM_BYTES);

    const float scale = 0.125f;  // DHEAD^-0.5
    dim3 gg(DIM / 128, MTOT / 128);   // (8, 64)

    gemm_tf32_kernel<<<gg, 256>>>(q, Wq, qh, MTOT, DIM, DIM, scale);
    gemm_tf32_kernel<<<gg, 256>>>(k, Wk, kh, MTOT, DIM, DIM, 1.0f);
    gemm_tf32_kernel<<<gg, 256>>>(v, Wv, vh, MTOT, DIM, DIM, 1.0f);

    flash_attn_kernel<<<dim3(SEQ / 128, HEADS, BATCH), 256, FA_SMEM_BYTES>>>(bias);

    gemm_tf32_kernel<<<gg, 256>>>(ao, Wo, out, MTOT, DIM, DIM, 1.0f);
}

// round 10
// speedup vs baseline: 1.5233x; 1.5233x over previous
#include <cuda_runtime.h>
#include <cuda_fp16.h>
#include <cstdint>
#include <math.h>

// Problem constants
#define BATCH 4
#define SEQ   2048
#define DIM   1024
#define HEADS 16
#define DHEAD 64
#define MTOT  (BATCH * SEQ)   // 8192

// ---------------------------------------------------------------------------
// Scratch (no cudaMalloc allowed). Intermediates in fp16; attention out fp32.
// ---------------------------------------------------------------------------
__device__ __half g_qh[(size_t)MTOT * DIM];
__device__ __half g_kh[(size_t)MTOT * DIM];
__device__ __half g_vh[(size_t)MTOT * DIM];
__device__ float  g_ao[(size_t)MTOT * DIM];

// ---------------------------------------------------------------------------
// helpers
// ---------------------------------------------------------------------------
__device__ __forceinline__ uint32_t cvt_h2(float lo, float hi) {
    uint32_t r;
    asm("cvt.rn.f16x2.f32 %0, %1, %2;" : "=r"(r) : "f"(hi), "f"(lo));
    return r;
}

// m16n8k16 fp16 MMA, fp32 accumulate
__device__ __forceinline__ void mma_f16(float c[4], const uint32_t a[4], const uint32_t b[2]) {
    asm volatile(
        "mma.sync.aligned.m16n8k16.row.col.f32.f16.f16.f32 "
        "{%0,%1,%2,%3}, {%4,%5,%6,%7}, {%8,%9}, {%0,%1,%2,%3};"
        : "+f"(c[0]), "+f"(c[1]), "+f"(c[2]), "+f"(c[3])
        : "r"(a[0]), "r"(a[1]), "r"(a[2]), "r"(a[3]),
          "r"(b[0]), "r"(b[1]));
}

// ---------------------------------------------------------------------------
// fp16 GEMM: C[M][N] = alpha * A[M][K] * Bw[N][K]^T  (A,Bw fp32; C fp32 or fp16)
// CTA tile 128x128, K-tile 32 (2 MMA k-steps), 256 threads, warp grid 2x4,
// warp tile 64x32. smem half tiles, row stride 20 words (40 halfs) -> the
// (4*gid + tig) conflict-free fragment bank pattern.
// ---------------------------------------------------------------------------
#define GH_S 20   // words per 32-half row (16 + pad 4)

template<typename OT>
__global__ __launch_bounds__(256) void gemm_h_kernel(
    const float* __restrict__ A, const float* __restrict__ Bw,
    OT* __restrict__ C, float alpha)
{
    __shared__ uint32_t sA[2][128 * GH_S];
    __shared__ uint32_t sB[2][128 * GH_S];

    const int tid  = threadIdx.x;
    const int m0   = blockIdx.y * 128;
    const int n0   = blockIdx.x * 128;
    const int lane = tid & 31, wid = tid >> 5;
    const int wr   = wid >> 2;        // 0..1
    const int wc   = wid & 3;         // 0..3
    const int gid  = lane >> 2, tig = lane & 3;

    const int frow = tid >> 1;        // 0..127
    const int fseg = tid & 1;         // 0..1  (16-float segment)

    float acc[4][4][4];
#pragma unroll
    for (int mt = 0; mt < 4; mt++)
#pragma unroll
        for (int nt = 0; nt < 4; nt++)
#pragma unroll
            for (int r = 0; r < 4; r++) acc[mt][nt][r] = 0.f;

    float4 fa[4], fb[4];

    // prologue: load k-tile 0
#pragma unroll
    for (int i = 0; i < 4; i++) {
        fa[i] = *reinterpret_cast<const float4*>(A  + (size_t)(m0 + frow) * DIM + fseg * 16 + i * 4);
        fb[i] = *reinterpret_cast<const float4*>(Bw + (size_t)(n0 + frow) * DIM + fseg * 16 + i * 4);
    }
    {
        uint32_t* pa = &sA[0][frow * GH_S + fseg * 8];
        uint32_t* pb = &sB[0][frow * GH_S + fseg * 8];
#pragma unroll
        for (int i = 0; i < 4; i++) {
            pa[i * 2]     = cvt_h2(fa[i].x, fa[i].y);
            pa[i * 2 + 1] = cvt_h2(fa[i].z, fa[i].w);
            pb[i * 2]     = cvt_h2(fb[i].x, fb[i].y);
            pb[i * 2 + 1] = cvt_h2(fb[i].z, fb[i].w);
        }
    }
    __syncthreads();

    const int NIT = DIM / 32;
    for (int t = 0; t < NIT; ++t) {
        const int cur = t & 1;
        if (t + 1 < NIT) {
            const int k0 = (t + 1) * 32;
#pragma unroll
            for (int i = 0; i < 4; i++) {
                fa[i] = *reinterpret_cast<const float4*>(A  + (size_t)(m0 + frow) * DIM + k0 + fseg * 16 + i * 4);
                fb[i] = *reinterpret_cast<const float4*>(Bw + (size_t)(n0 + frow) * DIM + k0 + fseg * 16 + i * 4);
            }
        }
#pragma unroll
        for (int kk = 0; kk < 2; kk++) {          // two m16n8k16 k-steps
            const int kw = kk * 8;
            uint32_t af[4][4], bf[4][2];
#pragma unroll
            for (int mt = 0; mt < 4; mt++) {
                const int r = wr * 64 + mt * 16;
                af[mt][0] = sA[cur][(r + gid)     * GH_S + kw + tig];
                af[mt][1] = sA[cur][(r + gid + 8) * GH_S + kw + tig];
                af[mt][2] = sA[cur][(r + gid)     * GH_S + kw + tig + 4];
                af[mt][3] = sA[cur][(r + gid + 8) * GH_S + kw + tig + 4];
            }
#pragma unroll
            for (int nt = 0; nt < 4; nt++) {
                const int c = wc * 32 + nt * 8;
                bf[nt][0] = sB[cur][(c + gid) * GH_S + kw + tig];
                bf[nt][1] = sB[cur][(c + gid) * GH_S + kw + tig + 4];
            }
#pragma unroll
            for (int mt = 0; mt < 4; mt++)
#pragma unroll
                for (int nt = 0; nt < 4; nt++)
                    mma_f16(acc[mt][nt], af[mt], bf[nt]);
        }
        if (t + 1 < NIT) {
            const int nxt = cur ^ 1;
            uint32_t* pa = &sA[nxt][frow * GH_S + fseg * 8];
            uint32_t* pb = &sB[nxt][frow * GH_S + fseg * 8];
#pragma unroll
            for (int i = 0; i < 4; i++) {
                pa[i * 2]     = cvt_h2(fa[i].x, fa[i].y);
                pa[i * 2 + 1] = cvt_h2(fa[i].z, fa[i].w);
                pb[i * 2]     = cvt_h2(fb[i].x, fb[i].y);
                pb[i * 2 + 1] = cvt_h2(fb[i].z, fb[i].w);
            }
        }
        __syncthreads();
    }

    // epilogue
#pragma unroll
    for (int mt = 0; mt < 4; mt++) {
        const int r = m0 + wr * 64 + mt * 16 + gid;
#pragma unroll
        for (int nt = 0; nt < 4; nt++) {
            const int c = n0 + wc * 32 + nt * 8 + tig * 2;
            float v0 = acc[mt][nt][0] * alpha, v1 = acc[mt][nt][1] * alpha;
            float v2 = acc[mt][nt][2] * alpha, v3 = acc[mt][nt][3] * alpha;
            if (sizeof(OT) == 2) {
                *reinterpret_cast<uint32_t*>((__half*)C + (size_t)r * DIM + c)       = cvt_h2(v0, v1);
                *reinterpret_cast<uint32_t*>((__half*)C + (size_t)(r + 8) * DIM + c) = cvt_h2(v2, v3);
            } else {
                *reinterpret_cast<float2*>((float*)C + (size_t)r * DIM + c)       = make_float2(v0, v1);
                *reinterpret_cast<float2*>((float*)C + (size_t)(r + 8) * DIM + c) = make_float2(v2, v3);
            }
        }
    }
}

// ---------------------------------------------------------------------------
// Flash attention v5 — fp16 m16n8k16, warp tile 16 rows x 64 cols, 8 warps.
// Q in registers for whole kernel (no Q smem). S C-frags ARE PV A-frags
// (same quad layout) -> P never touches smem. V pair-interleaved in smem.
// K/V double-buffered via register prefetch; ONE barrier per 64-col chunk.
// P scaled by 2^-6 before fp16 (cancels in O/l).
// ---------------------------------------------------------------------------
#define KSW 36   // words per 64-half K row (32 + pad 4)
#define VSW 72   // words per interleaved V pair-row (64 + pad 8)
#define LOG_PSCALE -4.1588830833596715f   // -6*ln2

__global__ __launch_bounds__(256, 2) void flash_attn_kernel(const float* __restrict__ bias)
{
    __shared__ uint32_t ksm[2][64 * KSW];
    __shared__ uint32_t vsm[2][32 * VSW];

    const int tid  = threadIdx.x;
    const int b    = blockIdx.x & 3;
    const int i0   = (blockIdx.x >> 2) * 128;
    const int h    = blockIdx.y;
    const int lane = tid & 31, wid = tid >> 5;
    const int gid  = lane >> 2, tig = lane & 3;
    const int hk   = h * DHEAD;

    // --- Q fragments: 16 regs, loaded once ---
    uint32_t qf[4][4];
    {
        const __half* qp = g_qh + ((size_t)(b * SEQ + i0 + wid * 16 + gid)) * DIM + hk;
#pragma unroll
        for (int kt = 0; kt < 4; kt++) {
            qf[kt][0] = *reinterpret_cast<const uint32_t*>(qp + kt * 16 + 2 * tig);
            qf[kt][1] = *reinterpret_cast<const uint32_t*>(qp + (size_t)8 * DIM + kt * 16 + 2 * tig);
            qf[kt][2] = *reinterpret_cast<const uint32_t*>(qp + kt * 16 + 8 + 2 * tig);
            qf[kt][3] = *reinterpret_cast<const uint32_t*>(qp + (size_t)8 * DIM + kt * 16 + 8 + 2 * tig);
        }
    }

    float oacc[8][4];
#pragma unroll
    for (int dt = 0; dt < 8; dt++)
#pragma unroll
        for (int r = 0; r < 4; r++) oacc[dt][r] = 0.f;
    float lacc0 = 0.f, lacc1 = 0.f;

    const float* biasrow = bias + ((size_t)h * SEQ + (i0 + wid * 16 + gid)) * SEQ;
    const __half* kroot = g_kh + ((size_t)(b * SEQ)) * DIM + hk;
    const __half* vroot = g_vh + ((size_t)(b * SEQ)) * DIM + hk;

    // K fill mapping: row=tid>>2 (0..63), seg=(tid&3)*16 halfs
    const int krow = tid >> 2, kseg = (tid & 3) * 16;
    // V fill mapping: jp=tid>>3 (0..31), dblk=(tid&7)*8 halfs
    const int vjp = tid >> 3, vdb = (tid & 7) * 8;

    // prologue: prefetch chunk 0
    uint4 ka0, ka1, vlo, vhi;
    ka0 = *reinterpret_cast<const uint4*>(kroot + (size_t)krow * DIM + kseg);
    ka1 = *reinterpret_cast<const uint4*>(kroot + (size_t)krow * DIM + kseg + 8);
    vlo = *reinterpret_cast<const uint4*>(vroot + (size_t)(2 * vjp) * DIM + vdb);
    vhi = *reinterpret_cast<const uint4*>(vroot + (size_t)(2 * vjp + 1) * DIM + vdb);

    for (int jc = 0; jc < SEQ / 64; ++jc) {
        const int j0  = jc * 64;
        const int cur = jc & 1;

        // ---- store prefetched K (natural) and V (pair-interleaved) ----
        {
            uint32_t* kd = &ksm[cur][krow * KSW + (tid & 3) * 8];
            *reinterpret_cast<uint4*>(kd)     = ka0;
            *reinterpret_cast<uint4*>(kd + 4) = ka1;
            uint32_t w0 = __byte_perm(vlo.x, vhi.x, 0x5410);
            uint32_t w1 = __byte_perm(vlo.x, vhi.x, 0x7632);
            uint32_t w2 = __byte_perm(vlo.y, vhi.y, 0x5410);
            uint32_t w3 = __byte_perm(vlo.y, vhi.y, 0x7632);
            uint32_t w4 = __byte_perm(vlo.z, vhi.z, 0x5410);
            uint32_t w5 = __byte_perm(vlo.z, vhi.z, 0x7632);
            uint32_t w6 = __byte_perm(vlo.w, vhi.w, 0x5410);
            uint32_t w7 = __byte_perm(vlo.w, vhi.w, 0x7632);
            uint32_t* vd = &vsm[cur][vjp * VSW + vdb];
            *reinterpret_cast<uint4*>(vd)     = make_uint4(w0, w1, w2, w3);
            *reinterpret_cast<uint4*>(vd + 4) = make_uint4(w4, w5, w6, w7);
        }
        __syncthreads();

        // ---- prefetch next chunk (hidden under MMA below) ----
        if (jc + 1 < SEQ / 64) {
            const __half* kb = kroot + (size_t)(j0 + 64) * DIM;
            const __half* vb = vroot + (size_t)(j0 + 64) * DIM;
            ka0 = *reinterpret_cast<const uint4*>(kb + (size_t)krow * DIM + kseg);
            ka1 = *reinterpret_cast<const uint4*>(kb + (size_t)krow * DIM + kseg + 8);
            vlo = *reinterpret_cast<const uint4*>(vb + (size_t)(2 * vjp) * DIM + vdb);
            vhi = *reinterpret_cast<const uint4*>(vb + (size_t)(2 * vjp + 1) * DIM + vdb);
        }

        // ---- bias fragments (issued early, consumed after S MMA) ----
        float2 bfr[8][2];
#pragma unroll
        for (int jt = 0; jt < 8; jt++) {
            bfr[jt][0] = *reinterpret_cast<const float2*>(biasrow + j0 + jt * 8 + 2 * tig);
            bfr[jt][1] = *reinterpret_cast<const float2*>(biasrow + (size_t)8 * SEQ + j0 + jt * 8 + 2 * tig);
        }

        // ---- S = q k^T  (warp: 16 rows x 64 cols) ----
        float sacc[8][4];
#pragma unroll
        for (int jt = 0; jt < 8; jt++)
#pragma unroll
            for (int r = 0; r < 4; r++) sacc[jt][r] = 0.f;

#pragma unroll
        for (int kt = 0; kt < 4; kt++) {
#pragma unroll
            for (int jt = 0; jt < 8; jt++) {
                uint32_t bf2[2];
                bf2[0] = ksm[cur][(jt * 8 + gid) * KSW + kt * 8 + tig];
                bf2[1] = ksm[cur][(jt * 8 + gid) * KSW + kt * 8 + tig + 4];
                mma_f16(sacc[jt], qf[kt], bf2);
            }
        }

        // ---- p = exp(s + bias + log(2^-6)) ; pack to fp16 A-frags ----
        uint32_t ph[8][2];
#pragma unroll
        for (int jt = 0; jt < 8; jt++) {
            float p0 = __expf(sacc[jt][0] + bfr[jt][0].x + LOG_PSCALE);
            float p1 = __expf(sacc[jt][1] + bfr[jt][0].y + LOG_PSCALE);
            float p2 = __expf(sacc[jt][2] + bfr[jt][1].x + LOG_PSCALE);
            float p3 = __expf(sacc[jt][3] + bfr[jt][1].y + LOG_PSCALE);
            lacc0 += p0 + p1;
            lacc1 += p2 + p3;
            ph[jt][0] = cvt_h2(p0, p1);
            ph[jt][1] = cvt_h2(p2, p3);
        }

        // ---- O += P V   (P from registers; V pair-interleaved smem) ----
#pragma unroll
        for (int kt = 0; kt < 4; kt++) {
            uint32_t a[4];
            a[0] = ph[2 * kt][0];
            a[1] = ph[2 * kt][1];
            a[2] = ph[2 * kt + 1][0];
            a[3] = ph[2 * kt + 1][1];
#pragma unroll
            for (int dt = 0; dt < 8; dt++) {
                uint32_t bf2[2];
                bf2[0] = vsm[cur][(8 * kt + tig)     * VSW + 8 * dt + gid];
                bf2[1] = vsm[cur][(8 * kt + 4 + tig) * VSW + 8 * dt + gid];
                mma_f16(oacc[dt], a, bf2);
            }
        }
    }

    // ---- row sums via quad shuffles (rows are warp-exclusive) ----
    lacc0 += __shfl_xor_sync(0xffffffffu, lacc0, 1);
    lacc0 += __shfl_xor_sync(0xffffffffu, lacc0, 2);
    lacc1 += __shfl_xor_sync(0xffffffffu, lacc1, 1);
    lacc1 += __shfl_xor_sync(0xffffffffu, lacc1, 2);
    const float inv0 = 1.f / lacc0;
    const float inv1 = 1.f / lacc1;

    float* obase = g_ao + ((size_t)(b * SEQ + i0 + wid * 16 + gid)) * DIM + hk;
#pragma unroll
    for (int dt = 0; dt < 8; dt++) {
        const int c = dt * 8 + 2 * tig;
        *reinterpret_cast<float2*>(obase + c) =
            make_float2(oacc[dt][0] * inv0, oacc[dt][1] * inv0);
        *reinterpret_cast<float2*>(obase + (size_t)8 * DIM + c) =
            make_float2(oacc[dt][2] * inv1, oacc[dt][3] * inv1);
    }
}

// ---------------------------------------------------------------------------
// launch
// ---------------------------------------------------------------------------
extern "C" void kernel_launch(void* const* d_in, const int* in_sizes, int n_in,
                              void* d_out, int out_size)
{
    (void)in_sizes; (void)n_in; (void)out_size;
    const float* q    = (const float*)d_in[0];
    const float* k    = (const float*)d_in[1];
    const float* v    = (const float*)d_in[2];
    const float* bias = (const float*)d_in[3];
    const float* Wq   = (const float*)d_in[4];
    const float* Wk   = (const float*)d_in[5];
    const float* Wv   = (const float*)d_in[6];
    const float* Wo   = (const float*)d_in[7];
    float* out        = (float*)d_out;

    __half *qh, *kh, *vh;
    float* ao;
    cudaGetSymbolAddress((void**)&qh, g_qh);
    cudaGetSymbolAddress((void**)&kh, g_kh);
    cudaGetSymbolAddress((void**)&vh, g_vh);
    cudaGetSymbolAddress((void**)&ao, g_ao);

    const float scale = 0.125f;  // DHEAD^-0.5
    dim3 gg(DIM / 128, MTOT / 128);   // (8, 64)

    gemm_h_kernel<__half><<<gg, 256>>>(q, Wq, qh, scale);
    gemm_h_kernel<__half><<<gg, 256>>>(k, Wk, kh, 1.0f);
    gemm_h_kernel<__half><<<gg, 256>>>(v, Wv, vh, 1.0f);

    // grid.x = (i-block, batch) with batch fastest -> bias L2 reuse across b
    flash_attn_kernel<<<dim3((SEQ / 128) * BATCH, HEADS), 256>>>(bias);

    gemm_h_kernel<float><<<gg, 256>>>(ao, Wo, out, 1.0f);
}

// round 11
// speedup vs baseline: 1.5602x; 1.0242x over previous
#include <cuda_runtime.h>
#include <cuda_fp16.h>
#include <cstdint>
#include <math.h>

// Problem constants
#define BATCH 4
#define SEQ   2048
#define DIM   1024
#define HEADS 16
#define DHEAD 64
#define MTOT  (BATCH * SEQ)   // 8192

// ---------------------------------------------------------------------------
// Scratch (no cudaMalloc allowed). Intermediates fp16; attention out fp32.
// ---------------------------------------------------------------------------
__device__ __half g_qh[(size_t)MTOT * DIM];
__device__ __half g_kh[(size_t)MTOT * DIM];
__device__ __half g_vh[(size_t)MTOT * DIM];
__device__ float  g_ao[(size_t)MTOT * DIM];

// ---------------------------------------------------------------------------
// helpers
// ---------------------------------------------------------------------------
__device__ __forceinline__ uint32_t cvt_h2(float lo, float hi) {
    uint32_t r;
    asm("cvt.rn.f16x2.f32 %0, %1, %2;" : "=r"(r) : "f"(hi), "f"(lo));
    return r;
}

__device__ __forceinline__ void mma_f16(float c[4], const uint32_t a[4], const uint32_t b[2]) {
    asm volatile(
        "mma.sync.aligned.m16n8k16.row.col.f32.f16.f16.f32 "
        "{%0,%1,%2,%3}, {%4,%5,%6,%7}, {%8,%9}, {%0,%1,%2,%3};"
        : "+f"(c[0]), "+f"(c[1]), "+f"(c[2]), "+f"(c[3])
        : "r"(a[0]), "r"(a[1]), "r"(a[2]), "r"(a[3]),
          "r"(b[0]), "r"(b[1]));
}

__device__ __forceinline__ void ldsm_x4(uint32_t& r0, uint32_t& r1, uint32_t& r2, uint32_t& r3,
                                        uint32_t addr) {
    asm volatile("ldmatrix.sync.aligned.m8n8.x4.shared.b16 {%0,%1,%2,%3}, [%4];"
        : "=r"(r0), "=r"(r1), "=r"(r2), "=r"(r3) : "r"(addr));
}
__device__ __forceinline__ void ldsm_x4_t(uint32_t& r0, uint32_t& r1, uint32_t& r2, uint32_t& r3,
                                          uint32_t addr) {
    asm volatile("ldmatrix.sync.aligned.m8n8.x4.trans.shared.b16 {%0,%1,%2,%3}, [%4];"
        : "=r"(r0), "=r"(r1), "=r"(r2), "=r"(r3) : "r"(addr));
}

// ---------------------------------------------------------------------------
// fp16 GEMM: C[M][N] = alpha * A[M][K] * Bw[N][K]^T  (A,Bw fp32; C fp32/fp16)
// CTA 128x128, K-tile 32, 256 threads, warp grid 2x4, warp tile 64x32.
// Fragments via ldmatrix.x4 (A non-trans on [m][k]; B non-trans on [n][k]).
// ---------------------------------------------------------------------------
#define GH_S 20   // words per 32-half row (16 + pad 4); stride bytes = 80

template<typename OT>
__global__ __launch_bounds__(256) void gemm_h_kernel(
    const float* __restrict__ A, const float* __restrict__ Bw,
    OT* __restrict__ C, float alpha)
{
    __shared__ uint32_t sA[2][128 * GH_S];
    __shared__ uint32_t sB[2][128 * GH_S];

    const int tid  = threadIdx.x;
    const int m0   = blockIdx.y * 128;
    const int n0   = blockIdx.x * 128;
    const int lane = tid & 31, wid = tid >> 5;
    const int wr   = wid >> 2;        // 0..1
    const int wc   = wid & 3;         // 0..3
    const int gid  = lane >> 2, tig = lane & 3;
    const int g    = lane >> 3, li = lane & 7;

    const uint32_t sA0 = (uint32_t)__cvta_generic_to_shared(&sA[0][0]);
    const uint32_t sB0 = (uint32_t)__cvta_generic_to_shared(&sB[0][0]);
    // A frag tiles order: (rows+0,kLo)(rows+8,kLo)(rows+0,kHi)(rows+8,kHi)
    //   lane -> row (g&1)*8+li, word (g>>1)*4
    const uint32_t a_lane = (uint32_t)(((g & 1) * 8 + li) * 80 + (g >> 1) * 16);
    // B frag x4 covers nt pair: (n+0,kLo)(n+0,kHi)(n+8,kLo)(n+8,kHi)
    //   lane -> row (g>>1)*8+li, word (g&1)*4
    const uint32_t b_lane = (uint32_t)(((g >> 1) * 8 + li) * 80 + (g & 1) * 16);

    const int frow = tid >> 1;        // 0..127
    const int fseg = tid & 1;         // 0..1

    float acc[4][4][4];
#pragma unroll
    for (int mt = 0; mt < 4; mt++)
#pragma unroll
        for (int nt = 0; nt < 4; nt++)
#pragma unroll
            for (int r = 0; r < 4; r++) acc[mt][nt][r] = 0.f;

    float4 fa[4], fb[4];

#pragma unroll
    for (int i = 0; i < 4; i++) {
        fa[i] = *reinterpret_cast<const float4*>(A  + (size_t)(m0 + frow) * DIM + fseg * 16 + i * 4);
        fb[i] = *reinterpret_cast<const float4*>(Bw + (size_t)(n0 + frow) * DIM + fseg * 16 + i * 4);
    }
    {
        uint32_t* pa = &sA[0][frow * GH_S + fseg * 8];
        uint32_t* pb = &sB[0][frow * GH_S + fseg * 8];
#pragma unroll
        for (int i = 0; i < 4; i++) {
            pa[i * 2]     = cvt_h2(fa[i].x, fa[i].y);
            pa[i * 2 + 1] = cvt_h2(fa[i].z, fa[i].w);
            pb[i * 2]     = cvt_h2(fb[i].x, fb[i].y);
            pb[i * 2 + 1] = cvt_h2(fb[i].z, fb[i].w);
        }
    }
    __syncthreads();

    const int NIT = DIM / 32;
    for (int t = 0; t < NIT; ++t) {
        const int cur = t & 1;
        if (t + 1 < NIT) {
            const int k0 = (t + 1) * 32;
#pragma unroll
            for (int i = 0; i < 4; i++) {
                fa[i] = *reinterpret_cast<const float4*>(A  + (size_t)(m0 + frow) * DIM + k0 + fseg * 16 + i * 4);
                fb[i] = *reinterpret_cast<const float4*>(Bw + (size_t)(n0 + frow) * DIM + k0 + fseg * 16 + i * 4);
            }
        }
        const uint32_t abase = sA0 + cur * (128 * GH_S * 4) + a_lane;
        const uint32_t bbase = sB0 + cur * (128 * GH_S * 4) + b_lane;
#pragma unroll
        for (int kk = 0; kk < 2; kk++) {          // two m16n8k16 k-steps
            uint32_t af[4][4], bf[4][2];
#pragma unroll
            for (int mt = 0; mt < 4; mt++)
                ldsm_x4(af[mt][0], af[mt][1], af[mt][2], af[mt][3],
                        abase + (uint32_t)((wr * 64 + mt * 16) * 80 + kk * 32));
#pragma unroll
            for (int p = 0; p < 2; p++)
                ldsm_x4(bf[2 * p][0], bf[2 * p][1], bf[2 * p + 1][0], bf[2 * p + 1][1],
                        bbase + (uint32_t)((wc * 32 + p * 16) * 80 + kk * 32));
#pragma unroll
            for (int mt = 0; mt < 4; mt++)
#pragma unroll
                for (int nt = 0; nt < 4; nt++)
                    mma_f16(acc[mt][nt], af[mt], bf[nt]);
        }
        if (t + 1 < NIT) {
            const int nxt = cur ^ 1;
            uint32_t* pa = &sA[nxt][frow * GH_S + fseg * 8];
            uint32_t* pb = &sB[nxt][frow * GH_S + fseg * 8];
#pragma unroll
            for (int i = 0; i < 4; i++) {
                pa[i * 2]     = cvt_h2(fa[i].x, fa[i].y);
                pa[i * 2 + 1] = cvt_h2(fa[i].z, fa[i].w);
                pb[i * 2]     = cvt_h2(fb[i].x, fb[i].y);
                pb[i * 2 + 1] = cvt_h2(fb[i].z, fb[i].w);
            }
        }
        __syncthreads();
    }

#pragma unroll
    for (int mt = 0; mt < 4; mt++) {
        const int r = m0 + wr * 64 + mt * 16 + gid;
#pragma unroll
        for (int nt = 0; nt < 4; nt++) {
            const int c = n0 + wc * 32 + nt * 8 + tig * 2;
            float v0 = acc[mt][nt][0] * alpha, v1 = acc[mt][nt][1] * alpha;
            float v2 = acc[mt][nt][2] * alpha, v3 = acc[mt][nt][3] * alpha;
            if (sizeof(OT) == 2) {
                *reinterpret_cast<uint32_t*>((__half*)C + (size_t)r * DIM + c)       = cvt_h2(v0, v1);
                *reinterpret_cast<uint32_t*>((__half*)C + (size_t)(r + 8) * DIM + c) = cvt_h2(v2, v3);
            } else {
                *reinterpret_cast<float2*>((float*)C + (size_t)r * DIM + c)       = make_float2(v0, v1);
                *reinterpret_cast<float2*>((float*)C + (size_t)(r + 8) * DIM + c) = make_float2(v2, v3);
            }
        }
    }
}

// ---------------------------------------------------------------------------
// Flash attention v6 — fp16 m16n8k16, warp tile 16 rows x 64 cols, 8 warps.
// Q in regs; P register-resident (S C-frags == PV A-frags).
// K and V both NATURAL [j][d] layout, stride 36 words.
// K B-frags: ldmatrix.x4 non-trans (memory [n][k]).
// V B-frags: ldmatrix.x4.trans  (memory [k][n]).  32 LDSM/chunk vs 128 LDS.
// ---------------------------------------------------------------------------
#define KVW 36   // words per 64-half row (32 + pad 4); 144 bytes

__global__ __launch_bounds__(256, 2) void flash_attn_kernel(const float* __restrict__ bias)
{
    __shared__ uint32_t ksm[2][64 * KVW];
    __shared__ uint32_t vsm[2][64 * KVW];

    const int tid  = threadIdx.x;
    const int b    = blockIdx.x & 3;
    const int i0   = (blockIdx.x >> 2) * 128;
    const int h    = blockIdx.y;
    const int lane = tid & 31, wid = tid >> 5;
    const int gid  = lane >> 2, tig = lane & 3;
    const int g    = lane >> 3, li = lane & 7;
    const int hk   = h * DHEAD;

    const uint32_t ks0 = (uint32_t)__cvta_generic_to_shared(&ksm[0][0]);
    const uint32_t vs0 = (uint32_t)__cvta_generic_to_shared(&vsm[0][0]);
    // K x4 covers jt pair: tiles (n+0,kLo)(n+0,kHi)(n+8,kLo)(n+8,kHi)
    const uint32_t k_lane = (uint32_t)(((g >> 1) * 8 + li) * 144 + (g & 1) * 16);
    // V x4.trans covers dt pair: tiles (kLo,n0)(kHi,n0)(kLo,n0+8)(kHi,n0+8)
    const uint32_t v_lane = (uint32_t)(((g & 1) * 8 + li) * 144 + (g >> 1) * 16);

    // --- Q fragments: 16 regs, loaded once ---
    uint32_t qf[4][4];
    {
        const __half* qp = g_qh + ((size_t)(b * SEQ + i0 + wid * 16 + gid)) * DIM + hk;
#pragma unroll
        for (int kt = 0; kt < 4; kt++) {
            qf[kt][0] = *reinterpret_cast<const uint32_t*>(qp + kt * 16 + 2 * tig);
            qf[kt][1] = *reinterpret_cast<const uint32_t*>(qp + (size_t)8 * DIM + kt * 16 + 2 * tig);
            qf[kt][2] = *reinterpret_cast<const uint32_t*>(qp + kt * 16 + 8 + 2 * tig);
            qf[kt][3] = *reinterpret_cast<const uint32_t*>(qp + (size_t)8 * DIM + kt * 16 + 8 + 2 * tig);
        }
    }

    float oacc[8][4];
#pragma unroll
    for (int dt = 0; dt < 8; dt++)
#pragma unroll
        for (int r = 0; r < 4; r++) oacc[dt][r] = 0.f;
    float lacc0 = 0.f, lacc1 = 0.f;

    const float* biasrow = bias + ((size_t)h * SEQ + (i0 + wid * 16 + gid)) * SEQ;
    const __half* kroot = g_kh + ((size_t)(b * SEQ)) * DIM + hk;
    const __half* vroot = g_vh + ((size_t)(b * SEQ)) * DIM + hk;

    // fill mapping: row = tid>>2 (0..63), 16-half segment = (tid&3)
    const int krow = tid >> 2, kseg = (tid & 3) * 16;

    // prologue: prefetch chunk 0
    uint4 ka0, ka1, va0, va1;
    ka0 = *reinterpret_cast<const uint4*>(kroot + (size_t)krow * DIM + kseg);
    ka1 = *reinterpret_cast<const uint4*>(kroot + (size_t)krow * DIM + kseg + 8);
    va0 = *reinterpret_cast<const uint4*>(vroot + (size_t)krow * DIM + kseg);
    va1 = *reinterpret_cast<const uint4*>(vroot + (size_t)krow * DIM + kseg + 8);

    for (int jc = 0; jc < SEQ / 64; ++jc) {
        const int j0  = jc * 64;
        const int cur = jc & 1;

        // ---- store prefetched K/V (both natural layout) ----
        {
            uint32_t* kd = &ksm[cur][krow * KVW + (tid & 3) * 8];
            *reinterpret_cast<uint4*>(kd)     = ka0;
            *reinterpret_cast<uint4*>(kd + 4) = ka1;
            uint32_t* vd = &vsm[cur][krow * KVW + (tid & 3) * 8];
            *reinterpret_cast<uint4*>(vd)     = va0;
            *reinterpret_cast<uint4*>(vd + 4) = va1;
        }
        __syncthreads();

        // ---- prefetch next chunk (hidden under MMA below) ----
        if (jc + 1 < SEQ / 64) {
            const __half* kb = kroot + (size_t)(j0 + 64) * DIM;
            const __half* vb = vroot + (size_t)(j0 + 64) * DIM;
            ka0 = *reinterpret_cast<const uint4*>(kb + (size_t)krow * DIM + kseg);
            ka1 = *reinterpret_cast<const uint4*>(kb + (size_t)krow * DIM + kseg + 8);
            va0 = *reinterpret_cast<const uint4*>(vb + (size_t)krow * DIM + kseg);
            va1 = *reinterpret_cast<const uint4*>(vb + (size_t)krow * DIM + kseg + 8);
        }

        // ---- bias fragments ----
        float2 bfr[8][2];
#pragma unroll
        for (int jt = 0; jt < 8; jt++) {
            bfr[jt][0] = *reinterpret_cast<const float2*>(biasrow + j0 + jt * 8 + 2 * tig);
            bfr[jt][1] = *reinterpret_cast<const float2*>(biasrow + (size_t)8 * SEQ + j0 + jt * 8 + 2 * tig);
        }

        // ---- S = q k^T ----
        float sacc[8][4];
#pragma unroll
        for (int jt = 0; jt < 8; jt++)
#pragma unroll
            for (int r = 0; r < 4; r++) sacc[jt][r] = 0.f;

        const uint32_t kbase = ks0 + cur * (64 * KVW * 4) + k_lane;
#pragma unroll
        for (int kt = 0; kt < 4; kt++) {
#pragma unroll
            for (int p = 0; p < 4; p++) {
                uint32_t b0, b1, b2, b3;
                ldsm_x4(b0, b1, b2, b3, kbase + (uint32_t)(p * 16 * 144 + kt * 32));
                { uint32_t bb[2] = {b0, b1}; mma_f16(sacc[2 * p],     qf[kt], bb); }
                { uint32_t bb[2] = {b2, b3}; mma_f16(sacc[2 * p + 1], qf[kt], bb); }
            }
        }

        // ---- p = exp(s + bias + log 2^-6); pack fp16 ----
        uint32_t ph[8][2];
#pragma unroll
        for (int jt = 0; jt < 8; jt++) {
            float p0 = __expf(sacc[jt][0] + bfr[jt][0].x - 4.1588830833596715f);
            float p1 = __expf(sacc[jt][1] + bfr[jt][0].y - 4.1588830833596715f);
            float p2 = __expf(sacc[jt][2] + bfr[jt][1].x - 4.1588830833596715f);
            float p3 = __expf(sacc[jt][3] + bfr[jt][1].y - 4.1588830833596715f);
            lacc0 += p0 + p1;
            lacc1 += p2 + p3;
            ph[jt][0] = cvt_h2(p0, p1);
            ph[jt][1] = cvt_h2(p2, p3);
        }

        // ---- O += P V  (V via ldmatrix.trans) ----
        const uint32_t vbase = vs0 + cur * (64 * KVW * 4) + v_lane;
#pragma unroll
        for (int kt = 0; kt < 4; kt++) {
            uint32_t a[4];
            a[0] = ph[2 * kt][0];
            a[1] = ph[2 * kt][1];
            a[2] = ph[2 * kt + 1][0];
            a[3] = ph[2 * kt + 1][1];
#pragma unroll
            for (int p = 0; p < 4; p++) {
                uint32_t b0, b1, b2, b3;
                ldsm_x4_t(b0, b1, b2, b3, vbase + (uint32_t)(kt * 16 * 144 + p * 32));
                { uint32_t bb[2] = {b0, b1}; mma_f16(oacc[2 * p],     a, bb); }
                { uint32_t bb[2] = {b2, b3}; mma_f16(oacc[2 * p + 1], a, bb); }
            }
        }
    }

    // ---- row sums via quad shuffles ----
    lacc0 += __shfl_xor_sync(0xffffffffu, lacc0, 1);
    lacc0 += __shfl_xor_sync(0xffffffffu, lacc0, 2);
    lacc1 += __shfl_xor_sync(0xffffffffu, lacc1, 1);
    lacc1 += __shfl_xor_sync(0xffffffffu, lacc1, 2);
    const float inv0 = 1.f / lacc0;
    const float inv1 = 1.f / lacc1;

    float* obase = g_ao + ((size_t)(b * SEQ + i0 + wid * 16 + gid)) * DIM + hk;
#pragma unroll
    for (int dt = 0; dt < 8; dt++) {
        const int c = dt * 8 + 2 * tig;
        *reinterpret_cast<float2*>(obase + c) =
            make_float2(oacc[dt][0] * inv0, oacc[dt][1] * inv0);
        *reinterpret_cast<float2*>(obase + (size_t)8 * DIM + c) =
            make_float2(oacc[dt][2] * inv1, oacc[dt][3] * inv1);
    }
}

// ---------------------------------------------------------------------------
// launch
// ---------------------------------------------------------------------------
extern "C" void kernel_launch(void* const* d_in, const int* in_sizes, int n_in,
                              void* d_out, int out_size)
{
    (void)in_sizes; (void)n_in; (void)out_size;
    const float* q    = (const float*)d_in[0];
    const float* k    = (const float*)d_in[1];
    const float* v    = (const float*)d_in[2];
    const float* bias = (const float*)d_in[3];
    const float* Wq   = (const float*)d_in[4];
    const float* Wk   = (const float*)d_in[5];
    const float* Wv   = (const float*)d_in[6];
    const float* Wo   = (const float*)d_in[7];
    float* out        = (float*)d_out;

    __half *qh, *kh, *vh;
    float* ao;
    cudaGetSymbolAddress((void**)&qh, g_qh);
    cudaGetSymbolAddress((void**)&kh, g_kh);
    cudaGetSymbolAddress((void**)&vh, g_vh);
    cudaGetSymbolAddress((void**)&ao, g_ao);

    const float scale = 0.125f;  // DHEAD^-0.5
    dim3 gg(DIM / 128, MTOT / 128);   // (8, 64)

    gemm_h_kernel<__half><<<gg, 256>>>(q, Wq, qh, scale);
    gemm_h_kernel<__half><<<gg, 256>>>(k, Wk, kh, 1.0f);
    gemm_h_kernel<__half><<<gg, 256>>>(v, Wv, vh, 1.0f);

    // grid.x = (i-block, batch) with batch fastest -> bias L2 reuse across b
    flash_attn_kernel<<<dim3((SEQ / 128) * BATCH, HEADS), 256>>>(bias);

    gemm_h_kernel<float><<<gg, 256>>>(ao, Wo, out, 1.0f);
}

// round 12
// speedup vs baseline: 1.9669x; 1.2607x over previous
#include <cuda_runtime.h>
#include <cuda_fp16.h>
#include <cstdint>
#include <math.h>

// Problem constants
#define BATCH 4
#define SEQ   2048
#define DIM   1024
#define HEADS 16
#define DHEAD 64
#define MTOT  (BATCH * SEQ)   // 8192

// ---------------------------------------------------------------------------
// Scratch (no cudaMalloc allowed)
// ---------------------------------------------------------------------------
__device__ __half g_q16[(size_t)MTOT * DIM];
__device__ __half g_k16[(size_t)MTOT * DIM];
__device__ __half g_v16[(size_t)MTOT * DIM];
__device__ __half g_w16[(size_t)4 * DIM * DIM];   // Wq,Wk,Wv,Wo
__device__ __half g_qh[(size_t)MTOT * DIM];
__device__ __half g_kh[(size_t)MTOT * DIM];
__device__ __half g_vh[(size_t)MTOT * DIM];
__device__ __half g_ao[(size_t)MTOT * DIM];

// ---------------------------------------------------------------------------
// helpers
// ---------------------------------------------------------------------------
__device__ __forceinline__ uint32_t cvt_h2(float lo, float hi) {
    uint32_t r;
    asm("cvt.rn.f16x2.f32 %0, %1, %2;" : "=r"(r) : "f"(hi), "f"(lo));
    return r;
}

__device__ __forceinline__ void mma_f16(float c[4], const uint32_t a[4], const uint32_t b[2]) {
    asm volatile(
        "mma.sync.aligned.m16n8k16.row.col.f32.f16.f16.f32 "
        "{%0,%1,%2,%3}, {%4,%5,%6,%7}, {%8,%9}, {%0,%1,%2,%3};"
        : "+f"(c[0]), "+f"(c[1]), "+f"(c[2]), "+f"(c[3])
        : "r"(a[0]), "r"(a[1]), "r"(a[2]), "r"(a[3]),
          "r"(b[0]), "r"(b[1]));
}

__device__ __forceinline__ void ldsm_x4(uint32_t& r0, uint32_t& r1, uint32_t& r2, uint32_t& r3,
                                        uint32_t addr) {
    asm volatile("ldmatrix.sync.aligned.m8n8.x4.shared.b16 {%0,%1,%2,%3}, [%4];"
        : "=r"(r0), "=r"(r1), "=r"(r2), "=r"(r3) : "r"(addr));
}
__device__ __forceinline__ void ldsm_x4_t(uint32_t& r0, uint32_t& r1, uint32_t& r2, uint32_t& r3,
                                          uint32_t addr) {
    asm volatile("ldmatrix.sync.aligned.m8n8.x4.trans.shared.b16 {%0,%1,%2,%3}, [%4];"
        : "=r"(r0), "=r"(r1), "=r"(r2), "=r"(r3) : "r"(addr));
}
__device__ __forceinline__ void cp16(uint32_t dst, const void* src) {
    asm volatile("cp.async.cg.shared.global [%0], [%1], 16;" :: "r"(dst), "l"(src));
}

// ---------------------------------------------------------------------------
// fp32 -> fp16 conversion (numerically identical to previous in-GEMM cvt)
// ---------------------------------------------------------------------------
__global__ __launch_bounds__(256) void cvt16_kernel(
    const float* __restrict__ src, __half* __restrict__ dst)
{
    const int i = blockIdx.x * 256 + threadIdx.x;
    float4 v = *reinterpret_cast<const float4*>(src + (size_t)i * 4);
    *reinterpret_cast<uint2*>(dst + (size_t)i * 4) =
        make_uint2(cvt_h2(v.x, v.y), cvt_h2(v.z, v.w));
}

// ---------------------------------------------------------------------------
// fp16 GEMM: C[M][N] = alpha * A[M][K] * B[N][K]^T   (A,B fp16; C fp16/fp32)
// CTA 128x256, 256 threads, warp grid 2x4, warp tile 64x64.
// K-tile 32, cp.async double-buffered. Fragments via ldmatrix.x4.
// ---------------------------------------------------------------------------
#define GH_S 20                    // words per 32-half row (16 + pad 4); 80 B
#define GA_W (128 * GH_S)          // A buffer words (one stage)
#define GB_W (256 * GH_S)          // B buffer words (one stage)
#define GT_SMEM_BYTES ((2 * GA_W + 2 * GB_W) * 4)   // 61440

template<typename OT>
__global__ __launch_bounds__(256, 1) void gemm_h_kernel(
    const __half* __restrict__ A, const __half* __restrict__ B,
    OT* __restrict__ C, float alpha)
{
    extern __shared__ char gsm[];
    const uint32_t s0 = (uint32_t)__cvta_generic_to_shared(gsm);
    const uint32_t sB0 = s0 + 2 * GA_W * 4;

    const int tid  = threadIdx.x;
    const int m0   = blockIdx.y * 128;
    const int n0   = blockIdx.x * 256;
    const int lane = tid & 31, wid = tid >> 5;
    const int wr   = wid >> 2;        // 0..1 -> 64-row half
    const int wc   = wid & 3;         // 0..3 -> 64-col quarter
    const int gid  = lane >> 2, tig = lane & 3;
    const int g    = lane >> 3, li = lane & 7;

    const uint32_t a_lane = (uint32_t)(((g & 1) * 8 + li) * 80 + (g >> 1) * 16);
    const uint32_t b_lane = (uint32_t)(((g >> 1) * 8 + li) * 80 + (g & 1) * 16);

    float acc[4][8][4];
#pragma unroll
    for (int mt = 0; mt < 4; mt++)
#pragma unroll
        for (int nt = 0; nt < 8; nt++)
#pragma unroll
            for (int r = 0; r < 4; r++) acc[mt][nt][r] = 0.f;

    // fill mappings: A row=idx>>2 (0..127) seg=idx&3 ; B row 0..255
    const int arow = tid >> 2, aseg = tid & 3;

    // prologue: issue k-tile 0
    {
        const uint32_t adst = s0;
#pragma unroll
        for (int i = 0; i < 2; i++) {
            int row = arow + i * 64;
            cp16(adst + (uint32_t)(row * 80 + aseg * 16),
                 A + (size_t)(m0 + row) * DIM + aseg * 8);
        }
#pragma unroll
        for (int i = 0; i < 4; i++) {
            int idx = tid + i * 256, row = idx >> 2, seg = idx & 3;
            cp16(sB0 + (uint32_t)(row * 80 + seg * 16),
                 B + (size_t)(n0 + row) * DIM + seg * 8);
        }
        asm volatile("cp.async.commit_group;");
    }

    const int NIT = DIM / 32;
    for (int t = 0; t < NIT; ++t) {
        const int cur = t & 1;
        if (t + 1 < NIT) {
            const int nb = cur ^ 1;
            const int k0 = (t + 1) * 32;
            const uint32_t adst = s0 + (uint32_t)(nb * GA_W * 4);
            const uint32_t bdst = sB0 + (uint32_t)(nb * GB_W * 4);
#pragma unroll
            for (int i = 0; i < 2; i++) {
                int row = arow + i * 64;
                cp16(adst + (uint32_t)(row * 80 + aseg * 16),
                     A + (size_t)(m0 + row) * DIM + k0 + aseg * 8);
            }
#pragma unroll
            for (int i = 0; i < 4; i++) {
                int idx = tid + i * 256, row = idx >> 2, seg = idx & 3;
                cp16(bdst + (uint32_t)(row * 80 + seg * 16),
                     B + (size_t)(n0 + row) * DIM + k0 + seg * 8);
            }
            asm volatile("cp.async.commit_group;");
            asm volatile("cp.async.wait_group 1;");
        } else {
            asm volatile("cp.async.wait_group 0;");
        }
        __syncthreads();

        const uint32_t abase = s0 + (uint32_t)(cur * GA_W * 4) + a_lane;
        const uint32_t bbase = sB0 + (uint32_t)(cur * GB_W * 4) + b_lane;
#pragma unroll
        for (int kk = 0; kk < 2; kk++) {
            uint32_t af[4][4], bf[8][2];
#pragma unroll
            for (int mt = 0; mt < 4; mt++)
                ldsm_x4(af[mt][0], af[mt][1], af[mt][2], af[mt][3],
                        abase + (uint32_t)((wr * 64 + mt * 16) * 80 + kk * 32));
#pragma unroll
            for (int p = 0; p < 4; p++)
                ldsm_x4(bf[2 * p][0], bf[2 * p][1], bf[2 * p + 1][0], bf[2 * p + 1][1],
                        bbase + (uint32_t)((wc * 64 + p * 16) * 80 + kk * 32));
#pragma unroll
            for (int mt = 0; mt < 4; mt++)
#pragma unroll
                for (int nt = 0; nt < 8; nt++)
                    mma_f16(acc[mt][nt], af[mt], bf[nt]);
        }
        __syncthreads();
    }

    // epilogue
#pragma unroll
    for (int mt = 0; mt < 4; mt++) {
        const int r = m0 + wr * 64 + mt * 16 + gid;
#pragma unroll
        for (int nt = 0; nt < 8; nt++) {
            const int c = n0 + wc * 64 + nt * 8 + tig * 2;
            float v0 = acc[mt][nt][0] * alpha, v1 = acc[mt][nt][1] * alpha;
            float v2 = acc[mt][nt][2] * alpha, v3 = acc[mt][nt][3] * alpha;
            if (sizeof(OT) == 2) {
                *reinterpret_cast<uint32_t*>((__half*)C + (size_t)r * DIM + c)       = cvt_h2(v0, v1);
                *reinterpret_cast<uint32_t*>((__half*)C + (size_t)(r + 8) * DIM + c) = cvt_h2(v2, v3);
            } else {
                *reinterpret_cast<float2*>((float*)C + (size_t)r * DIM + c)       = make_float2(v0, v1);
                *reinterpret_cast<float2*>((float*)C + (size_t)(r + 8) * DIM + c) = make_float2(v2, v3);
            }
        }
    }
}

// ---------------------------------------------------------------------------
// Flash attention v7 — warp tile 32 q-rows x 64 j-cols, 8 warps (CTA 256 rows).
// K/V smem traffic per warp unchanged but covers 2x rows -> crossbar bytes/row
// halved. S/exp/PV processed in two 32-col halves to bound registers.
// Q + P register-resident. Single barrier per chunk (reg-prefetch K/V).
// ---------------------------------------------------------------------------
#define KVW 36   // words per 64-half row; 144 B stride

__global__ __launch_bounds__(256, 1) void flash_attn_kernel(const float* __restrict__ bias)
{
    __shared__ uint32_t ksm[2][64 * KVW];
    __shared__ uint32_t vsm[2][64 * KVW];

    const int tid  = threadIdx.x;
    const int b    = blockIdx.x & 3;
    const int i0   = (blockIdx.x >> 2) * 256;
    const int h    = blockIdx.y;
    const int lane = tid & 31, wid = tid >> 5;
    const int gid  = lane >> 2, tig = lane & 3;
    const int g    = lane >> 3, li = lane & 7;
    const int hk   = h * DHEAD;

    const uint32_t ks0 = (uint32_t)__cvta_generic_to_shared(&ksm[0][0]);
    const uint32_t vs0 = (uint32_t)__cvta_generic_to_shared(&vsm[0][0]);
    const uint32_t k_lane = (uint32_t)(((g >> 1) * 8 + li) * 144 + (g & 1) * 16);
    const uint32_t v_lane = (uint32_t)(((g & 1) * 8 + li) * 144 + (g >> 1) * 16);

    // --- Q fragments: 2 m-tiles x 4 k-tiles, loaded once (32 regs) ---
    uint32_t qf[2][4][4];
#pragma unroll
    for (int mt = 0; mt < 2; mt++) {
        const __half* qp = g_qh + ((size_t)(b * SEQ + i0 + wid * 32 + mt * 16 + gid)) * DIM + hk;
#pragma unroll
        for (int kt = 0; kt < 4; kt++) {
            qf[mt][kt][0] = *reinterpret_cast<const uint32_t*>(qp + kt * 16 + 2 * tig);
            qf[mt][kt][1] = *reinterpret_cast<const uint32_t*>(qp + (size_t)8 * DIM + kt * 16 + 2 * tig);
            qf[mt][kt][2] = *reinterpret_cast<const uint32_t*>(qp + kt * 16 + 8 + 2 * tig);
            qf[mt][kt][3] = *reinterpret_cast<const uint32_t*>(qp + (size_t)8 * DIM + kt * 16 + 8 + 2 * tig);
        }
    }

    float oacc[2][8][4];
#pragma unroll
    for (int mt = 0; mt < 2; mt++)
#pragma unroll
        for (int dt = 0; dt < 8; dt++)
#pragma unroll
            for (int r = 0; r < 4; r++) oacc[mt][dt][r] = 0.f;
    float lacc[2][2] = {{0.f, 0.f}, {0.f, 0.f}};

    const __half* kroot = g_kh + ((size_t)(b * SEQ)) * DIM + hk;
    const __half* vroot = g_vh + ((size_t)(b * SEQ)) * DIM + hk;
    const size_t bias_r0 = ((size_t)h * SEQ + (i0 + wid * 32 + gid)) * SEQ;

    const int krow = tid >> 2, kseg = (tid & 3) * 16;

    // prologue: prefetch chunk 0
    uint4 ka0, ka1, va0, va1;
    ka0 = *reinterpret_cast<const uint4*>(kroot + (size_t)krow * DIM + kseg);
    ka1 = *reinterpret_cast<const uint4*>(kroot + (size_t)krow * DIM + kseg + 8);
    va0 = *reinterpret_cast<const uint4*>(vroot + (size_t)krow * DIM + kseg);
    va1 = *reinterpret_cast<const uint4*>(vroot + (size_t)krow * DIM + kseg + 8);

    for (int jc = 0; jc < SEQ / 64; ++jc) {
        const int j0  = jc * 64;
        const int cur = jc & 1;

        // store prefetched K/V
        {
            uint32_t* kd = &ksm[cur][krow * KVW + (tid & 3) * 8];
            *reinterpret_cast<uint4*>(kd)     = ka0;
            *reinterpret_cast<uint4*>(kd + 4) = ka1;
            uint32_t* vd = &vsm[cur][krow * KVW + (tid & 3) * 8];
            *reinterpret_cast<uint4*>(vd)     = va0;
            *reinterpret_cast<uint4*>(vd + 4) = va1;
        }
        __syncthreads();

        // prefetch next chunk
        if (jc + 1 < SEQ / 64) {
            const __half* kb = kroot + (size_t)(j0 + 64) * DIM;
            const __half* vb = vroot + (size_t)(j0 + 64) * DIM;
            ka0 = *reinterpret_cast<const uint4*>(kb + (size_t)krow * DIM + kseg);
            ka1 = *reinterpret_cast<const uint4*>(kb + (size_t)krow * DIM + kseg + 8);
            va0 = *reinterpret_cast<const uint4*>(vb + (size_t)krow * DIM + kseg);
            va1 = *reinterpret_cast<const uint4*>(vb + (size_t)krow * DIM + kseg + 8);
        }

        const uint32_t kbase = ks0 + cur * (64 * KVW * 4) + k_lane;
        const uint32_t vbase = vs0 + cur * (64 * KVW * 4) + v_lane;

#pragma unroll
        for (int ha = 0; ha < 2; ha++) {        // two 32-col halves
            // bias fragments for this half (32 floats, transient)
            float2 bfr[2][4][2];
#pragma unroll
            for (int mt = 0; mt < 2; mt++) {
                const float* br = bias + bias_r0 + (size_t)mt * 16 * SEQ;
#pragma unroll
                for (int jt = 0; jt < 4; jt++) {
                    const int c = j0 + ha * 32 + jt * 8 + 2 * tig;
                    bfr[mt][jt][0] = *reinterpret_cast<const float2*>(br + c);
                    bfr[mt][jt][1] = *reinterpret_cast<const float2*>(br + (size_t)8 * SEQ + c);
                }
            }

            // S = q k^T for this half
            float sacc[2][4][4];
#pragma unroll
            for (int mt = 0; mt < 2; mt++)
#pragma unroll
                for (int jt = 0; jt < 4; jt++)
#pragma unroll
                    for (int r = 0; r < 4; r++) sacc[mt][jt][r] = 0.f;

#pragma unroll
            for (int kt = 0; kt < 4; kt++) {
#pragma unroll
                for (int p = 0; p < 2; p++) {
                    uint32_t b0, b1, b2, b3;
                    ldsm_x4(b0, b1, b2, b3,
                            kbase + (uint32_t)((ha * 2 + p) * 16 * 144 + kt * 32));
#pragma unroll
                    for (int mt = 0; mt < 2; mt++) {
                        { uint32_t bb[2] = {b0, b1}; mma_f16(sacc[mt][2 * p],     qf[mt][kt], bb); }
                        { uint32_t bb[2] = {b2, b3}; mma_f16(sacc[mt][2 * p + 1], qf[mt][kt], bb); }
                    }
                }
            }

            // p = exp(s + bias + log 2^-6); pack fp16
            uint32_t ph[2][4][2];
#pragma unroll
            for (int mt = 0; mt < 2; mt++)
#pragma unroll
                for (int jt = 0; jt < 4; jt++) {
                    float p0 = __expf(sacc[mt][jt][0] + bfr[mt][jt][0].x - 4.1588830833596715f);
                    float p1 = __expf(sacc[mt][jt][1] + bfr[mt][jt][0].y - 4.1588830833596715f);
                    float p2 = __expf(sacc[mt][jt][2] + bfr[mt][jt][1].x - 4.1588830833596715f);
                    float p3 = __expf(sacc[mt][jt][3] + bfr[mt][jt][1].y - 4.1588830833596715f);
                    lacc[mt][0] += p0 + p1;
                    lacc[mt][1] += p2 + p3;
                    ph[mt][jt][0] = cvt_h2(p0, p1);
                    ph[mt][jt][1] = cvt_h2(p2, p3);
                }

            // O += P V for this half (k-steps 2*ha .. 2*ha+1)
#pragma unroll
            for (int ktl = 0; ktl < 2; ktl++) {
                const int kt = ha * 2 + ktl;
#pragma unroll
                for (int p = 0; p < 4; p++) {
                    uint32_t b0, b1, b2, b3;
                    ldsm_x4_t(b0, b1, b2, b3,
                              vbase + (uint32_t)(kt * 16 * 144 + p * 32));
#pragma unroll
                    for (int mt = 0; mt < 2; mt++) {
                        uint32_t a[4];
                        a[0] = ph[mt][2 * ktl][0];
                        a[1] = ph[mt][2 * ktl][1];
                        a[2] = ph[mt][2 * ktl + 1][0];
                        a[3] = ph[mt][2 * ktl + 1][1];
                        { uint32_t bb[2] = {b0, b1}; mma_f16(oacc[mt][2 * p],     a, bb); }
                        { uint32_t bb[2] = {b2, b3}; mma_f16(oacc[mt][2 * p + 1], a, bb); }
                    }
                }
            }
        }
    }

    // row sums via quad shuffles; write O (fp16) to g_ao
#pragma unroll
    for (int mt = 0; mt < 2; mt++) {
#pragma unroll
        for (int r = 0; r < 2; r++) {
            lacc[mt][r] += __shfl_xor_sync(0xffffffffu, lacc[mt][r], 1);
            lacc[mt][r] += __shfl_xor_sync(0xffffffffu, lacc[mt][r], 2);
        }
        const float inv0 = 1.f / lacc[mt][0];
        const float inv1 = 1.f / lacc[mt][1];
        __half* obase = g_ao + ((size_t)(b * SEQ + i0 + wid * 32 + mt * 16 + gid)) * DIM + hk;
#pragma unroll
        for (int dt = 0; dt < 8; dt++) {
            const int c = dt * 8 + 2 * tig;
            *reinterpret_cast<uint32_t*>(obase + c) =
                cvt_h2(oacc[mt][dt][0] * inv0, oacc[mt][dt][1] * inv0);
            *reinterpret_cast<uint32_t*>(obase + (size_t)8 * DIM + c) =
                cvt_h2(oacc[mt][dt][2] * inv1, oacc[mt][dt][3] * inv1);
        }
    }
}

// ---------------------------------------------------------------------------
// launch
// ---------------------------------------------------------------------------
extern "C" void kernel_launch(void* const* d_in, const int* in_sizes, int n_in,
                              void* d_out, int out_size)
{
    (void)in_sizes; (void)n_in; (void)out_size;
    const float* q    = (const float*)d_in[0];
    const float* k    = (const float*)d_in[1];
    const float* v    = (const float*)d_in[2];
    const float* bias = (const float*)d_in[3];
    const float* Wq   = (const float*)d_in[4];
    const float* Wk   = (const float*)d_in[5];
    const float* Wv   = (const float*)d_in[6];
    const float* Wo   = (const float*)d_in[7];
    float* out        = (float*)d_out;

    __half *q16, *k16, *v16, *w16, *qh, *kh, *vh, *ao;
    cudaGetSymbolAddress((void**)&q16, g_q16);
    cudaGetSymbolAddress((void**)&k16, g_k16);
    cudaGetSymbolAddress((void**)&v16, g_v16);
    cudaGetSymbolAddress((void**)&w16, g_w16);
    cudaGetSymbolAddress((void**)&qh, g_qh);
    cudaGetSymbolAddress((void**)&kh, g_kh);
    cudaGetSymbolAddress((void**)&vh, g_vh);
    cudaGetSymbolAddress((void**)&ao, g_ao);

    cudaFuncSetAttribute(gemm_h_kernel<__half>,
                         cudaFuncAttributeMaxDynamicSharedMemorySize, GT_SMEM_BYTES);
    cudaFuncSetAttribute(gemm_h_kernel<float>,
                         cudaFuncAttributeMaxDynamicSharedMemorySize, GT_SMEM_BYTES);

    const float scale = 0.125f;  // DHEAD^-0.5
    const int NB = (MTOT * DIM) / 4 / 256;   // 8192 blocks for activations
    const int WB = (DIM * DIM) / 4 / 256;    // 1024 blocks per weight

    cvt16_kernel<<<NB, 256>>>(q, q16);
    cvt16_kernel<<<NB, 256>>>(k, k16);
    cvt16_kernel<<<NB, 256>>>(v, v16);
    cvt16_kernel<<<WB, 256>>>(Wq, w16);
    cvt16_kernel<<<WB, 256>>>(Wk, w16 + (size_t)DIM * DIM);
    cvt16_kernel<<<WB, 256>>>(Wv, w16 + (size_t)2 * DIM * DIM);
    cvt16_kernel<<<WB, 256>>>(Wo, w16 + (size_t)3 * DIM * DIM);

    dim3 gg(DIM / 256, MTOT / 128);   // (4, 64)
    gemm_h_kernel<__half><<<gg, 256, GT_SMEM_BYTES>>>(q16, w16, qh, scale);
    gemm_h_kernel<__half><<<gg, 256, GT_SMEM_BYTES>>>(k16, w16 + (size_t)DIM * DIM, kh, 1.0f);
    gemm_h_kernel<__half><<<gg, 256, GT_SMEM_BYTES>>>(v16, w16 + (size_t)2 * DIM * DIM, vh, 1.0f);

    // grid.x = (i-block, batch) with batch fastest -> bias L2 reuse across b
    flash_attn_kernel<<<dim3((SEQ / 256) * BATCH, HEADS), 256>>>(bias);

    gemm_h_kernel<float><<<gg, 256, GT_SMEM_BYTES>>>(ao, w16 + (size_t)3 * DIM * DIM, out, 1.0f);
}

// round 15
// speedup vs baseline: 2.0534x; 1.0439x over previous
#include <cuda_runtime.h>
#include <cuda_fp16.h>
#include <cstdint>
#include <math.h>

// Problem constants
#define BATCH 4
#define SEQ   2048
#define DIM   1024
#define HEADS 16
#define DHEAD 64
#define MTOT  (BATCH * SEQ)   // 8192

// ---------------------------------------------------------------------------
// Scratch (no cudaMalloc allowed)
// ---------------------------------------------------------------------------
__device__ __half g_q16[(size_t)MTOT * DIM];
__device__ __half g_k16[(size_t)MTOT * DIM];
__device__ __half g_v16[(size_t)MTOT * DIM];
__device__ __half g_w16[(size_t)4 * DIM * DIM];   // Wq,Wk,Wv,Wo
__device__ __half g_qh[(size_t)MTOT * DIM];
__device__ __half g_kh[(size_t)MTOT * DIM];
__device__ __half g_vh[(size_t)MTOT * DIM];
__device__ __half g_ao[(size_t)MTOT * DIM];

// ---------------------------------------------------------------------------
// helpers
// ---------------------------------------------------------------------------
__device__ __forceinline__ uint32_t cvt_h2(float lo, float hi) {
    uint32_t r;
    asm("cvt.rn.f16x2.f32 %0, %1, %2;" : "=r"(r) : "f"(hi), "f"(lo));
    return r;
}

__device__ __forceinline__ void mma_f16(float c[4], const uint32_t a[4], const uint32_t b[2]) {
    asm volatile(
        "mma.sync.aligned.m16n8k16.row.col.f32.f16.f16.f32 "
        "{%0,%1,%2,%3}, {%4,%5,%6,%7}, {%8,%9}, {%0,%1,%2,%3};"
        : "+f"(c[0]), "+f"(c[1]), "+f"(c[2]), "+f"(c[3])
        : "r"(a[0]), "r"(a[1]), "r"(a[2]), "r"(a[3]),
          "r"(b[0]), "r"(b[1]));
}

__device__ __forceinline__ void ldsm_x4(uint32_t& r0, uint32_t& r1, uint32_t& r2, uint32_t& r3,
                                        uint32_t addr) {
    asm volatile("ldmatrix.sync.aligned.m8n8.x4.shared.b16 {%0,%1,%2,%3}, [%4];"
        : "=r"(r0), "=r"(r1), "=r"(r2), "=r"(r3) : "r"(addr));
}
__device__ __forceinline__ void ldsm_x4_t(uint32_t& r0, uint32_t& r1, uint32_t& r2, uint32_t& r3,
                                          uint32_t addr) {
    asm volatile("ldmatrix.sync.aligned.m8n8.x4.trans.shared.b16 {%0,%1,%2,%3}, [%4];"
        : "=r"(r0), "=r"(r1), "=r"(r2), "=r"(r3) : "r"(addr));
}
__device__ __forceinline__ void cp16(uint32_t dst, const void* src) {
    asm volatile("cp.async.cg.shared.global [%0], [%1], 16;" :: "r"(dst), "l"(src));
}

// ---------------------------------------------------------------------------
// fp32 -> fp16 conversion, merged launches
// ---------------------------------------------------------------------------
__global__ __launch_bounds__(256) void cvt16_qkv_kernel(
    const float* __restrict__ q, const float* __restrict__ k, const float* __restrict__ v,
    __half* __restrict__ q16, __half* __restrict__ k16, __half* __restrict__ v16)
{
    const float* src = (blockIdx.y == 0) ? q : (blockIdx.y == 1) ? k : v;
    __half* dst      = (blockIdx.y == 0) ? q16 : (blockIdx.y == 1) ? k16 : v16;
    const int i = blockIdx.x * 256 + threadIdx.x;
    float4 x = *reinterpret_cast<const float4*>(src + (size_t)i * 4);
    *reinterpret_cast<uint2*>(dst + (size_t)i * 4) =
        make_uint2(cvt_h2(x.x, x.y), cvt_h2(x.z, x.w));
}

__global__ __launch_bounds__(256) void cvt16_w_kernel(
    const float* __restrict__ w0, const float* __restrict__ w1,
    const float* __restrict__ w2, const float* __restrict__ w3,
    __half* __restrict__ dst)
{
    const float* src = (blockIdx.y == 0) ? w0 : (blockIdx.y == 1) ? w1
                     : (blockIdx.y == 2) ? w2 : w3;
    const int i = blockIdx.x * 256 + threadIdx.x;
    float4 x = *reinterpret_cast<const float4*>(src + (size_t)i * 4);
    *reinterpret_cast<uint2*>(dst + (size_t)blockIdx.y * DIM * DIM + (size_t)i * 4) =
        make_uint2(cvt_h2(x.x, x.y), cvt_h2(x.z, x.w));
}

// ---------------------------------------------------------------------------
// fp16 GEMM: C[M][N] = alpha * A[M][K] * B[N][K]^T   (A,B fp16; C fp16/fp32)
// CTA 128x256, 256 threads, warp grid 2x4, warp tile 64x64.
// K-tile 32, cp.async 3-STAGE pipeline: wait(1) -> sync -> issue(t+2) -> MMA(t)
// so each tile's load has a full k-tile of compute to hide under.
// ---------------------------------------------------------------------------
#define GH_S 20                         // words per 32-half row (16 + pad 4)
#define GSW ((128 + 256) * GH_S)        // words per stage = 7680
#define GT_SMEM_BYTES (3 * GSW * 4)     // 92160

template<typename OT>
__global__ __launch_bounds__(256, 1) void gemm_h_kernel(
    const __half* __restrict__ A, const __half* __restrict__ B,
    OT* __restrict__ C, float alpha)
{
    extern __shared__ char gsm[];
    const uint32_t s0 = (uint32_t)__cvta_generic_to_shared(gsm);

    const int tid  = threadIdx.x;
    const int m0   = blockIdx.y * 128;
    const int n0   = blockIdx.x * 256;
    const int lane = tid & 31, wid = tid >> 5;
    const int wr   = wid >> 2;        // 0..1 -> 64-row half
    const int wc   = wid & 3;         // 0..3 -> 64-col quarter
    const int gid  = lane >> 2, tig = lane & 3;
    const int g    = lane >> 3, li = lane & 7;

    const uint32_t a_lane = (uint32_t)(((g & 1) * 8 + li) * 80 + (g >> 1) * 16);
    const uint32_t b_lane = (uint32_t)(((g >> 1) * 8 + li) * 80 + (g & 1) * 16);

    const int arow = tid >> 2, aseg = tid & 3;

    float acc[4][8][4];
#pragma unroll
    for (int mt = 0; mt < 4; mt++)
#pragma unroll
        for (int nt = 0; nt < 8; nt++)
#pragma unroll
            for (int r = 0; r < 4; r++) acc[mt][nt][r] = 0.f;

    // stage issue helper
    auto issue_tile = [&](int stg, int k0) {
        const uint32_t adst = s0 + (uint32_t)(stg * GSW * 4);
        const uint32_t bdst = adst + (uint32_t)(128 * GH_S * 4);
#pragma unroll
        for (int i = 0; i < 2; i++) {
            int row = arow + i * 64;
            cp16(adst + (uint32_t)(row * 80 + aseg * 16),
                 A + (size_t)(m0 + row) * DIM + k0 + aseg * 8);
        }
#pragma unroll
        for (int i = 0; i < 4; i++) {
            int idx = tid + i * 256, row = idx >> 2, seg = idx & 3;
            cp16(bdst + (uint32_t)(row * 80 + seg * 16),
                 B + (size_t)(n0 + row) * DIM + k0 + seg * 8);
        }
    };

    // prologue: tiles 0 and 1 in flight
    issue_tile(0, 0);
    asm volatile("cp.async.commit_group;");
    issue_tile(1, 32);
    asm volatile("cp.async.commit_group;");

    const int NIT = DIM / 32;
    for (int t = 0; t < NIT; ++t) {
        asm volatile("cp.async.wait_group 1;");
        __syncthreads();

        if (t + 2 < NIT) issue_tile((t + 2) % 3, (t + 2) * 32);
        asm volatile("cp.async.commit_group;");

        const uint32_t abase = s0 + (uint32_t)((t % 3) * GSW * 4) + a_lane;
        const uint32_t bbase = s0 + (uint32_t)((t % 3) * GSW * 4 + 128 * GH_S * 4) + b_lane;
#pragma unroll
        for (int kk = 0; kk < 2; kk++) {
            uint32_t af[4][4], bf[8][2];
#pragma unroll
            for (int mt = 0; mt < 4; mt++)
                ldsm_x4(af[mt][0], af[mt][1], af[mt][2], af[mt][3],
                        abase + (uint32_t)((wr * 64 + mt * 16) * 80 + kk * 32));
#pragma unroll
            for (int p = 0; p < 4; p++)
                ldsm_x4(bf[2 * p][0], bf[2 * p][1], bf[2 * p + 1][0], bf[2 * p + 1][1],
                        bbase + (uint32_t)((wc * 64 + p * 16) * 80 + kk * 32));
#pragma unroll
            for (int mt = 0; mt < 4; mt++)
#pragma unroll
                for (int nt = 0; nt < 8; nt++)
                    mma_f16(acc[mt][nt], af[mt], bf[nt]);
        }
    }

    // epilogue
#pragma unroll
    for (int mt = 0; mt < 4; mt++) {
        const int r = m0 + wr * 64 + mt * 16 + gid;
#pragma unroll
        for (int nt = 0; nt < 8; nt++) {
            const int c = n0 + wc * 64 + nt * 8 + tig * 2;
            float v0 = acc[mt][nt][0] * alpha, v1 = acc[mt][nt][1] * alpha;
            float v2 = acc[mt][nt][2] * alpha, v3 = acc[mt][nt][3] * alpha;
            if (sizeof(OT) == 2) {
                *reinterpret_cast<uint32_t*>((__half*)C + (size_t)r * DIM + c)       = cvt_h2(v0, v1);
                *reinterpret_cast<uint32_t*>((__half*)C + (size_t)(r + 8) * DIM + c) = cvt_h2(v2, v3);
            } else {
                *reinterpret_cast<float2*>((float*)C + (size_t)r * DIM + c)       = make_float2(v0, v1);
                *reinterpret_cast<float2*>((float*)C + (size_t)(r + 8) * DIM + c) = make_float2(v2, v3);
            }
        }
    }
}

// ---------------------------------------------------------------------------
// Flash attention v8 — warp tile 32 q-rows x 64 j-cols, 8 warps (CTA 256 rows).
// K/V via cp.async 2-stage: wait(0) -> sync -> issue(jc+1) -> MMA(jc).
// Q + P register-resident; one barrier per chunk.
// Dynamic smem: K stages @0,9216 ; V stages @18432,27648 (36864 B total).
// ---------------------------------------------------------------------------
#define KVW 36            // words per 64-half row; 144 B stride
#define FKV_STG 9216      // bytes per stage (64 rows * 144 B)

__global__ __launch_bounds__(256, 1) void flash_attn_kernel(const float* __restrict__ bias)
{
    extern __shared__ char fsm[];
    const uint32_t s0 = (uint32_t)__cvta_generic_to_shared(fsm);

    const int tid  = threadIdx.x;
    const int b    = blockIdx.x & 3;
    const int i0   = (blockIdx.x >> 2) * 256;
    const int h    = blockIdx.y;
    const int lane = tid & 31, wid = tid >> 5;
    const int gid  = lane >> 2, tig = lane & 3;
    const int g    = lane >> 3, li = lane & 7;
    const int hk   = h * DHEAD;

    const uint32_t k_lane = (uint32_t)(((g >> 1) * 8 + li) * 144 + (g & 1) * 16);
    const uint32_t v_lane = (uint32_t)(((g & 1) * 8 + li) * 144 + (g >> 1) * 16);

    // --- Q fragments: 2 m-tiles x 4 k-tiles, loaded once (32 regs) ---
    uint32_t qf[2][4][4];
#pragma unroll
    for (int mt = 0; mt < 2; mt++) {
        const __half* qp = g_qh + ((size_t)(b * SEQ + i0 + wid * 32 + mt * 16 + gid)) * DIM + hk;
#pragma unroll
        for (int kt = 0; kt < 4; kt++) {
            qf[mt][kt][0] = *reinterpret_cast<const uint32_t*>(qp + kt * 16 + 2 * tig);
            qf[mt][kt][1] = *reinterpret_cast<const uint32_t*>(qp + (size_t)8 * DIM + kt * 16 + 2 * tig);
            qf[mt][kt][2] = *reinterpret_cast<const uint32_t*>(qp + kt * 16 + 8 + 2 * tig);
            qf[mt][kt][3] = *reinterpret_cast<const uint32_t*>(qp + (size_t)8 * DIM + kt * 16 + 8 + 2 * tig);
        }
    }

    float oacc[2][8][4];
#pragma unroll
    for (int mt = 0; mt < 2; mt++)
#pragma unroll
        for (int dt = 0; dt < 8; dt++)
#pragma unroll
            for (int r = 0; r < 4; r++) oacc[mt][dt][r] = 0.f;
    float lacc[2][2] = {{0.f, 0.f}, {0.f, 0.f}};

    const __half* kroot = g_kh + ((size_t)(b * SEQ)) * DIM + hk;
    const __half* vroot = g_vh + ((size_t)(b * SEQ)) * DIM + hk;
    const size_t bias_r0 = ((size_t)h * SEQ + (i0 + wid * 32 + gid)) * SEQ;

    // fill mapping: idx -> row = idx>>3 (0..63), seg = idx&7 (16B units)
    const int frow0 = tid >> 3, fseg = tid & 7;

    auto issue_chunk = [&](int stg, int j0) {
        const uint32_t kdst = s0 + (uint32_t)(stg * FKV_STG);
        const uint32_t vdst = s0 + (uint32_t)(2 * FKV_STG + stg * FKV_STG);
#pragma unroll
        for (int i = 0; i < 2; i++) {
            int row = frow0 + i * 32;
            cp16(kdst + (uint32_t)(row * 144 + fseg * 16),
                 kroot + (size_t)(j0 + row) * DIM + fseg * 8);
            cp16(vdst + (uint32_t)(row * 144 + fseg * 16),
                 vroot + (size_t)(j0 + row) * DIM + fseg * 8);
        }
    };

    issue_chunk(0, 0);
    asm volatile("cp.async.commit_group;");

    const int NC = SEQ / 64;
    for (int jc = 0; jc < NC; ++jc) {
        const int j0  = jc * 64;
        const int cur = jc & 1;

        asm volatile("cp.async.wait_group 0;");
        __syncthreads();

        if (jc + 1 < NC) issue_chunk(cur ^ 1, j0 + 64);
        asm volatile("cp.async.commit_group;");

        const uint32_t kbase = s0 + (uint32_t)(cur * FKV_STG) + k_lane;
        const uint32_t vbase = s0 + (uint32_t)(2 * FKV_STG + cur * FKV_STG) + v_lane;

#pragma unroll
        for (int ha = 0; ha < 2; ha++) {        // two 32-col halves
            // bias fragments for this half
            float2 bfr[2][4][2];
#pragma unroll
            for (int mt = 0; mt < 2; mt++) {
                const float* br = bias + bias_r0 + (size_t)mt * 16 * SEQ;
#pragma unroll
                for (int jt = 0; jt < 4; jt++) {
                    const int c = j0 + ha * 32 + jt * 8 + 2 * tig;
                    bfr[mt][jt][0] = *reinterpret_cast<const float2*>(br + c);
                    bfr[mt][jt][1] = *reinterpret_cast<const float2*>(br + (size_t)8 * SEQ + c);
                }
            }

            // S = q k^T for this half
            float sacc[2][4][4];
#pragma unroll
            for (int mt = 0; mt < 2; mt++)
#pragma unroll
                for (int jt = 0; jt < 4; jt++)
#pragma unroll
                    for (int r = 0; r < 4; r++) sacc[mt][jt][r] = 0.f;

#pragma unroll
            for (int kt = 0; kt < 4; kt++) {
#pragma unroll
                for (int p = 0; p < 2; p++) {
                    uint32_t b0, b1, b2, b3;
                    ldsm_x4(b0, b1, b2, b3,
                            kbase + (uint32_t)((ha * 2 + p) * 16 * 144 + kt * 32));
#pragma unroll
                    for (int mt = 0; mt < 2; mt++) {
                        { uint32_t bb[2] = {b0, b1}; mma_f16(sacc[mt][2 * p],     qf[mt][kt], bb); }
                        { uint32_t bb[2] = {b2, b3}; mma_f16(sacc[mt][2 * p + 1], qf[mt][kt], bb); }
                    }
                }
            }

            // p = exp(s + bias + log 2^-6); pack fp16
            uint32_t ph[2][4][2];
#pragma unroll
            for (int mt = 0; mt < 2; mt++)
#pragma unroll
                for (int jt = 0; jt < 4; jt++) {
                    float p0 = __expf(sacc[mt][jt][0] + bfr[mt][jt][0].x - 4.1588830833596715f);
                    float p1 = __expf(sacc[mt][jt][1] + bfr[mt][jt][0].y - 4.1588830833596715f);
                    float p2 = __expf(sacc[mt][jt][2] + bfr[mt][jt][1].x - 4.1588830833596715f);
                    float p3 = __expf(sacc[mt][jt][3] + bfr[mt][jt][1].y - 4.1588830833596715f);
                    lacc[mt][0] += p0 + p1;
                    lacc[mt][1] += p2 + p3;
                    ph[mt][jt][0] = cvt_h2(p0, p1);
                    ph[mt][jt][1] = cvt_h2(p2, p3);
                }

            // O += P V for this half (k-steps 2*ha .. 2*ha+1)
#pragma unroll
            for (int ktl = 0; ktl < 2; ktl++) {
                const int kt = ha * 2 + ktl;
#pragma unroll
                for (int p = 0; p < 4; p++) {
                    uint32_t b0, b1, b2, b3;
                    ldsm_x4_t(b0, b1, b2, b3,
                              vbase + (uint32_t)(kt * 16 * 144 + p * 32));
#pragma unroll
                    for (int mt = 0; mt < 2; mt++) {
                        uint32_t a[4];
                        a[0] = ph[mt][2 * ktl][0];
                        a[1] = ph[mt][2 * ktl][1];
                        a[2] = ph[mt][2 * ktl + 1][0];
                        a[3] = ph[mt][2 * ktl + 1][1];
                        { uint32_t bb[2] = {b0, b1}; mma_f16(oacc[mt][2 * p],     a, bb); }
                        { uint32_t bb[2] = {b2, b3}; mma_f16(oacc[mt][2 * p + 1], a, bb); }
                    }
                }
            }
        }
    }

    // row sums via quad shuffles; write O (fp16) to g_ao
#pragma unroll
    for (int mt = 0; mt < 2; mt++) {
#pragma unroll
        for (int r = 0; r < 2; r++) {
            lacc[mt][r] += __shfl_xor_sync(0xffffffffu, lacc[mt][r], 1);
            lacc[mt][r] += __shfl_xor_sync(0xffffffffu, lacc[mt][r], 2);
        }
        const float inv0 = 1.f / lacc[mt][0];
        const float inv1 = 1.f / lacc[mt][1];
        __half* obase = g_ao + ((size_t)(b * SEQ + i0 + wid * 32 + mt * 16 + gid)) * DIM + hk;
#pragma unroll
        for (int dt = 0; dt < 8; dt++) {
            const int c = dt * 8 + 2 * tig;
            *reinterpret_cast<uint32_t*>(obase + c) =
                cvt_h2(oacc[mt][dt][0] * inv0, oacc[mt][dt][1] * inv0);
            *reinterpret_cast<uint32_t*>(obase + (size_t)8 * DIM + c) =
                cvt_h2(oacc[mt][dt][2] * inv1, oacc[mt][dt][3] * inv1);
        }
    }
}

// ---------------------------------------------------------------------------
// launch
// ---------------------------------------------------------------------------
extern "C" void kernel_launch(void* const* d_in, const int* in_sizes, int n_in,
                              void* d_out, int out_size)
{
    (void)in_sizes; (void)n_in; (void)out_size;
    const float* q    = (const float*)d_in[0];
    const float* k    = (const float*)d_in[1];
    const float* v    = (const float*)d_in[2];
    const float* bias = (const float*)d_in[3];
    const float* Wq   = (const float*)d_in[4];
    const float* Wk   = (const float*)d_in[5];
    const float* Wv   = (const float*)d_in[6];
    const float* Wo   = (const float*)d_in[7];
    float* out        = (float*)d_out;

    __half *q16, *k16, *v16, *w16, *qh, *kh, *vh, *ao;
    cudaGetSymbolAddress((void**)&q16, g_q16);
    cudaGetSymbolAddress((void**)&k16, g_k16);
    cudaGetSymbolAddress((void**)&v16, g_v16);
    cudaGetSymbolAddress((void**)&w16, g_w16);
    cudaGetSymbolAddress((void**)&qh, g_qh);
    cudaGetSymbolAddress((void**)&kh, g_kh);
    cudaGetSymbolAddress((void**)&vh, g_vh);
    cudaGetSymbolAddress((void**)&ao, g_ao);

    cudaFuncSetAttribute(gemm_h_kernel<__half>,
                         cudaFuncAttributeMaxDynamicSharedMemorySize, GT_SMEM_BYTES);
    cudaFuncSetAttribute(gemm_h_kernel<float>,
                         cudaFuncAttributeMaxDynamicSharedMemorySize, GT_SMEM_BYTES);

    const float scale = 0.125f;  // DHEAD^-0.5
    const int NB = (MTOT * DIM) / 4 / 256;   // 8192
    const int WB = (DIM * DIM) / 4 / 256;    // 1024

    cvt16_qkv_kernel<<<dim3(NB, 3), 256>>>(q, k, v, q16, k16, v16);
    cvt16_w_kernel<<<dim3(WB, 4), 256>>>(Wq, Wk, Wv, Wo, w16);

    dim3 gg(DIM / 256, MTOT / 128);   // (4, 64)
    gemm_h_kernel<__half><<<gg, 256, GT_SMEM_BYTES>>>(q16, w16, qh, scale);
    gemm_h_kernel<__half><<<gg, 256, GT_SMEM_BYTES>>>(k16, w16 + (size_t)DIM * DIM, kh, 1.0f);
    gemm_h_kernel<__half><<<gg, 256, GT_SMEM_BYTES>>>(v16, w16 + (size_t)2 * DIM * DIM, vh, 1.0f);

    // grid.x = (i-block, batch) with batch fastest -> bias L2 reuse across b
    flash_attn_kernel<<<dim3((SEQ / 256) * BATCH, HEADS), 256, 4 * FKV_STG>>>(bias);

    gemm_h_kernel<float><<<gg, 256, GT_SMEM_BYTES>>>(ao, w16 + (size_t)3 * DIM * DIM, out, 1.0f);
}

// round 17
// speedup vs baseline: 2.0996x; 1.0225x over previous
#include <cuda_runtime.h>
#include <cuda_fp16.h>
#include <cstdint>
#include <math.h>

// Problem constants
#define BATCH 4
#define SEQ   2048
#define DIM   1024
#define HEADS 16
#define DHEAD 64
#define MTOT  (BATCH * SEQ)   // 8192

// ---------------------------------------------------------------------------
// Scratch (no cudaMalloc allowed)
// ---------------------------------------------------------------------------
__device__ __half g_q16[(size_t)MTOT * DIM];
__device__ __half g_k16[(size_t)MTOT * DIM];
__device__ __half g_v16[(size_t)MTOT * DIM];
__device__ __half g_w16[(size_t)4 * DIM * DIM];   // Wq,Wk,Wv,Wo
__device__ __half g_qh[(size_t)MTOT * DIM];
__device__ __half g_kh[(size_t)MTOT * DIM];
__device__ __half g_vh[(size_t)MTOT * DIM];
__device__ __half g_ao[(size_t)MTOT * DIM];

// ---------------------------------------------------------------------------
// helpers
// ---------------------------------------------------------------------------
__device__ __forceinline__ uint32_t cvt_h2(float lo, float hi) {
    uint32_t r;
    asm("cvt.rn.f16x2.f32 %0, %1, %2;" : "=r"(r) : "f"(hi), "f"(lo));
    return r;
}

__device__ __forceinline__ void mma_f16(float c[4], const uint32_t a[4], const uint32_t b[2]) {
    asm volatile(
        "mma.sync.aligned.m16n8k16.row.col.f32.f16.f16.f32 "
        "{%0,%1,%2,%3}, {%4,%5,%6,%7}, {%8,%9}, {%0,%1,%2,%3};"
        : "+f"(c[0]), "+f"(c[1]), "+f"(c[2]), "+f"(c[3])
        : "r"(a[0]), "r"(a[1]), "r"(a[2]), "r"(a[3]),
          "r"(b[0]), "r"(b[1]));
}

__device__ __forceinline__ void ldsm_x4(uint32_t& r0, uint32_t& r1, uint32_t& r2, uint32_t& r3,
                                        uint32_t addr) {
    asm volatile("ldmatrix.sync.aligned.m8n8.x4.shared.b16 {%0,%1,%2,%3}, [%4];"
        : "=r"(r0), "=r"(r1), "=r"(r2), "=r"(r3) : "r"(addr));
}
__device__ __forceinline__ void ldsm_x4_t(uint32_t& r0, uint32_t& r1, uint32_t& r2, uint32_t& r3,
                                          uint32_t addr) {
    asm volatile("ldmatrix.sync.aligned.m8n8.x4.trans.shared.b16 {%0,%1,%2,%3}, [%4];"
        : "=r"(r0), "=r"(r1), "=r"(r2), "=r"(r3) : "r"(addr));
}
__device__ __forceinline__ void cp16(uint32_t dst, const void* src) {
    asm volatile("cp.async.cg.shared.global [%0], [%1], 16;" :: "r"(dst), "l"(src));
}

// ---------------------------------------------------------------------------
// fp32 -> fp16 conversion, merged launches
// ---------------------------------------------------------------------------
__global__ __launch_bounds__(256) void cvt16_qkv_kernel(
    const float* __restrict__ q, const float* __restrict__ k, const float* __restrict__ v,
    __half* __restrict__ q16, __half* __restrict__ k16, __half* __restrict__ v16)
{
    const float* src = (blockIdx.y == 0) ? q : (blockIdx.y == 1) ? k : v;
    __half* dst      = (blockIdx.y == 0) ? q16 : (blockIdx.y == 1) ? k16 : v16;
    const int i = blockIdx.x * 256 + threadIdx.x;
    float4 x = *reinterpret_cast<const float4*>(src + (size_t)i * 4);
    *reinterpret_cast<uint2*>(dst + (size_t)i * 4) =
        make_uint2(cvt_h2(x.x, x.y), cvt_h2(x.z, x.w));
}

__global__ __launch_bounds__(256) void cvt16_w_kernel(
    const float* __restrict__ w0, const float* __restrict__ w1,
    const float* __restrict__ w2, const float* __restrict__ w3,
    __half* __restrict__ dst)
{
    const float* src = (blockIdx.y == 0) ? w0 : (blockIdx.y == 1) ? w1
                     : (blockIdx.y == 2) ? w2 : w3;
    const int i = blockIdx.x * 256 + threadIdx.x;
    float4 x = *reinterpret_cast<const float4*>(src + (size_t)i * 4);
    *reinterpret_cast<uint2*>(dst + (size_t)blockIdx.y * DIM * DIM + (size_t)i * 4) =
        make_uint2(cvt_h2(x.x, x.y), cvt_h2(x.z, x.w));
}

// ---------------------------------------------------------------------------
// fp16 GEMM: C[M][N] = alpha * A[M][K] * B[N][K]^T   (A,B fp16; C fp16/fp32)
// CTA 128x256, 512 threads (16 warps, grid 2x8), warp tile 64x32.
// K-tile 32, cp.async 3-STAGE pipeline: wait(1) -> sync -> issue(t+2) -> MMA(t).
// 16 warps = 4/SMSP to hide HMMA latency (R14: 8 warps left tensor at 37%).
// ---------------------------------------------------------------------------
#define GH_S 20                         // words per 32-half row (16 + pad 4)
#define GSW ((128 + 256) * GH_S)        // words per stage = 7680
#define GT_SMEM_BYTES (3 * GSW * 4)     // 92160

template<typename OT>
__global__ __launch_bounds__(512, 1) void gemm_h_kernel(
    const __half* __restrict__ A, const __half* __restrict__ B,
    OT* __restrict__ C, float alpha)
{
    extern __shared__ char gsm[];
    const uint32_t s0 = (uint32_t)__cvta_generic_to_shared(gsm);

    const int tid  = threadIdx.x;
    const int m0   = blockIdx.y * 128;
    const int n0   = blockIdx.x * 256;
    const int lane = tid & 31, wid = tid >> 5;
    const int wr   = wid >> 3;        // 0..1 -> 64-row half
    const int wc   = wid & 7;         // 0..7 -> 32-col slice
    const int gid  = lane >> 2, tig = lane & 3;
    const int g    = lane >> 3, li = lane & 7;

    const uint32_t a_lane = (uint32_t)(((g & 1) * 8 + li) * 80 + (g >> 1) * 16);
    const uint32_t b_lane = (uint32_t)(((g >> 1) * 8 + li) * 80 + (g & 1) * 16);

    // fill mapping (512 threads): A row = tid>>2 (0..127), seg = tid&3 (1 cp16)
    //                             B rows via 2 iters of idx>>2 (0..255)
    const int arow = tid >> 2, aseg = tid & 3;

    float acc[4][4][4];
#pragma unroll
    for (int mt = 0; mt < 4; mt++)
#pragma unroll
        for (int nt = 0; nt < 4; nt++)
#pragma unroll
            for (int r = 0; r < 4; r++) acc[mt][nt][r] = 0.f;

    auto issue_tile = [&](int stg, int k0) {
        const uint32_t adst = s0 + (uint32_t)(stg * GSW * 4);
        const uint32_t bdst = adst + (uint32_t)(128 * GH_S * 4);
        cp16(adst + (uint32_t)(arow * 80 + aseg * 16),
             A + (size_t)(m0 + arow) * DIM + k0 + aseg * 8);
#pragma unroll
        for (int i = 0; i < 2; i++) {
            int idx = tid + i * 512, row = idx >> 2, seg = idx & 3;
            cp16(bdst + (uint32_t)(row * 80 + seg * 16),
                 B + (size_t)(n0 + row) * DIM + k0 + seg * 8);
        }
    };

    // prologue: tiles 0 and 1 in flight
    issue_tile(0, 0);
    asm volatile("cp.async.commit_group;");
    issue_tile(1, 32);
    asm volatile("cp.async.commit_group;");

    const int NIT = DIM / 32;
    for (int t = 0; t < NIT; ++t) {
        asm volatile("cp.async.wait_group 1;");
        __syncthreads();

        if (t + 2 < NIT) issue_tile((t + 2) % 3, (t + 2) * 32);
        asm volatile("cp.async.commit_group;");

        const uint32_t abase = s0 + (uint32_t)((t % 3) * GSW * 4) + a_lane;
        const uint32_t bbase = s0 + (uint32_t)((t % 3) * GSW * 4 + 128 * GH_S * 4) + b_lane;
#pragma unroll
        for (int kk = 0; kk < 2; kk++) {
            uint32_t af[4][4], bf[4][2];
#pragma unroll
            for (int mt = 0; mt < 4; mt++)
                ldsm_x4(af[mt][0], af[mt][1], af[mt][2], af[mt][3],
                        abase + (uint32_t)((wr * 64 + mt * 16) * 80 + kk * 32));
#pragma unroll
            for (int p = 0; p < 2; p++)
                ldsm_x4(bf[2 * p][0], bf[2 * p][1], bf[2 * p + 1][0], bf[2 * p + 1][1],
                        bbase + (uint32_t)((wc * 32 + p * 16) * 80 + kk * 32));
#pragma unroll
            for (int mt = 0; mt < 4; mt++)
#pragma unroll
                for (int nt = 0; nt < 4; nt++)
                    mma_f16(acc[mt][nt], af[mt], bf[nt]);
        }
    }

    // epilogue
#pragma unroll
    for (int mt = 0; mt < 4; mt++) {
        const int r = m0 + wr * 64 + mt * 16 + gid;
#pragma unroll
        for (int nt = 0; nt < 4; nt++) {
            const int c = n0 + wc * 32 + nt * 8 + tig * 2;
            float v0 = acc[mt][nt][0] * alpha, v1 = acc[mt][nt][1] * alpha;
            float v2 = acc[mt][nt][2] * alpha, v3 = acc[mt][nt][3] * alpha;
            if (sizeof(OT) == 2) {
                *reinterpret_cast<uint32_t*>((__half*)C + (size_t)r * DIM + c)       = cvt_h2(v0, v1);
                *reinterpret_cast<uint32_t*>((__half*)C + (size_t)(r + 8) * DIM + c) = cvt_h2(v2, v3);
            } else {
                *reinterpret_cast<float2*>((float*)C + (size_t)r * DIM + c)       = make_float2(v0, v1);
                *reinterpret_cast<float2*>((float*)C + (size_t)(r + 8) * DIM + c) = make_float2(v2, v3);
            }
        }
    }
}

// ---------------------------------------------------------------------------
// Flash attention v8 — unchanged from R14 (warp tile 32x64, cp.async 2-stage).
// ---------------------------------------------------------------------------
#define KVW 36            // words per 64-half row; 144 B stride
#define FKV_STG 9216      // bytes per stage (64 rows * 144 B)

__global__ __launch_bounds__(256, 1) void flash_attn_kernel(const float* __restrict__ bias)
{
    extern __shared__ char fsm[];
    const uint32_t s0 = (uint32_t)__cvta_generic_to_shared(fsm);

    const int tid  = threadIdx.x;
    const int b    = blockIdx.x & 3;
    const int i0   = (blockIdx.x >> 2) * 256;
    const int h    = blockIdx.y;
    const int lane = tid & 31, wid = tid >> 5;
    const int gid  = lane >> 2, tig = lane & 3;
    const int g    = lane >> 3, li = lane & 7;
    const int hk   = h * DHEAD;

    const uint32_t k_lane = (uint32_t)(((g >> 1) * 8 + li) * 144 + (g & 1) * 16);
    const uint32_t v_lane = (uint32_t)(((g & 1) * 8 + li) * 144 + (g >> 1) * 16);

    // --- Q fragments: 2 m-tiles x 4 k-tiles, loaded once (32 regs) ---
    uint32_t qf[2][4][4];
#pragma unroll
    for (int mt = 0; mt < 2; mt++) {
        const __half* qp = g_qh + ((size_t)(b * SEQ + i0 + wid * 32 + mt * 16 + gid)) * DIM + hk;
#pragma unroll
        for (int kt = 0; kt < 4; kt++) {
            qf[mt][kt][0] = *reinterpret_cast<const uint32_t*>(qp + kt * 16 + 2 * tig);
            qf[mt][kt][1] = *reinterpret_cast<const uint32_t*>(qp + (size_t)8 * DIM + kt * 16 + 2 * tig);
            qf[mt][kt][2] = *reinterpret_cast<const uint32_t*>(qp + kt * 16 + 8 + 2 * tig);
            qf[mt][kt][3] = *reinterpret_cast<const uint32_t*>(qp + (size_t)8 * DIM + kt * 16 + 8 + 2 * tig);
        }
    }

    float oacc[2][8][4];
#pragma unroll
    for (int mt = 0; mt < 2; mt++)
#pragma unroll
        for (int dt = 0; dt < 8; dt++)
#pragma unroll
            for (int r = 0; r < 4; r++) oacc[mt][dt][r] = 0.f;
    float lacc[2][2] = {{0.f, 0.f}, {0.f, 0.f}};

    const __half* kroot = g_kh + ((size_t)(b * SEQ)) * DIM + hk;
    const __half* vroot = g_vh + ((size_t)(b * SEQ)) * DIM + hk;
    const size_t bias_r0 = ((size_t)h * SEQ + (i0 + wid * 32 + gid)) * SEQ;

    const int frow0 = tid >> 3, fseg = tid & 7;

    auto issue_chunk = [&](int stg, int j0) {
        const uint32_t kdst = s0 + (uint32_t)(stg * FKV_STG);
        const uint32_t vdst = s0 + (uint32_t)(2 * FKV_STG + stg * FKV_STG);
#pragma unroll
        for (int i = 0; i < 2; i++) {
            int row = frow0 + i * 32;
            cp16(kdst + (uint32_t)(row * 144 + fseg * 16),
                 kroot + (size_t)(j0 + row) * DIM + fseg * 8);
            cp16(vdst + (uint32_t)(row * 144 + fseg * 16),
                 vroot + (size_t)(j0 + row) * DIM + fseg * 8);
        }
    };

    issue_chunk(0, 0);
    asm volatile("cp.async.commit_group;");

    const int NC = SEQ / 64;
    for (int jc = 0; jc < NC; ++jc) {
        const int j0  = jc * 64;
        const int cur = jc & 1;

        asm volatile("cp.async.wait_group 0;");
        __syncthreads();

        if (jc + 1 < NC) issue_chunk(cur ^ 1, j0 + 64);
        asm volatile("cp.async.commit_group;");

        const uint32_t kbase = s0 + (uint32_t)(cur * FKV_STG) + k_lane;
        const uint32_t vbase = s0 + (uint32_t)(2 * FKV_STG + cur * FKV_STG) + v_lane;

#pragma unroll
        for (int ha = 0; ha < 2; ha++) {        // two 32-col halves
            float2 bfr[2][4][2];
#pragma unroll
            for (int mt = 0; mt < 2; mt++) {
                const float* br = bias + bias_r0 + (size_t)mt * 16 * SEQ;
#pragma unroll
                for (int jt = 0; jt < 4; jt++) {
                    const int c = j0 + ha * 32 + jt * 8 + 2 * tig;
                    bfr[mt][jt][0] = *reinterpret_cast<const float2*>(br + c);
                    bfr[mt][jt][1] = *reinterpret_cast<const float2*>(br + (size_t)8 * SEQ + c);
                }
            }

            float sacc[2][4][4];
#pragma unroll
            for (int mt = 0; mt < 2; mt++)
#pragma unroll
                for (int jt = 0; jt < 4; jt++)
#pragma unroll
                    for (int r = 0; r < 4; r++) sacc[mt][jt][r] = 0.f;

#pragma unroll
            for (int kt = 0; kt < 4; kt++) {
#pragma unroll
                for (int p = 0; p < 2; p++) {
                    uint32_t b0, b1, b2, b3;
                    ldsm_x4(b0, b1, b2, b3,
                            kbase + (uint32_t)((ha * 2 + p) * 16 * 144 + kt * 32));
#pragma unroll
                    for (int mt = 0; mt < 2; mt++) {
                        { uint32_t bb[2] = {b0, b1}; mma_f16(sacc[mt][2 * p],     qf[mt][kt], bb); }
                        { uint32_t bb[2] = {b2, b3}; mma_f16(sacc[mt][2 * p + 1], qf[mt][kt], bb); }
                    }
                }
            }

            uint32_t ph[2][4][2];
#pragma unroll
            for (int mt = 0; mt < 2; mt++)
#pragma unroll
                for (int jt = 0; jt < 4; jt++) {
                    float p0 = __expf(sacc[mt][jt][0] + bfr[mt][jt][0].x - 4.1588830833596715f);
                    float p1 = __expf(sacc[mt][jt][1] + bfr[mt][jt][0].y - 4.1588830833596715f);
                    float p2 = __expf(sacc[mt][jt][2] + bfr[mt][jt][1].x - 4.1588830833596715f);
                    float p3 = __expf(sacc[mt][jt][3] + bfr[mt][jt][1].y - 4.1588830833596715f);
                    lacc[mt][0] += p0 + p1;
                    lacc[mt][1] += p2 + p3;
                    ph[mt][jt][0] = cvt_h2(p0, p1);
                    ph[mt][jt][1] = cvt_h2(p2, p3);
                }

#pragma unroll
            for (int ktl = 0; ktl < 2; ktl++) {
                const int kt = ha * 2 + ktl;
#pragma unroll
                for (int p = 0; p < 4; p++) {
                    uint32_t b0, b1, b2, b3;
                    ldsm_x4_t(b0, b1, b2, b3,
                              vbase + (uint32_t)(kt * 16 * 144 + p * 32));
#pragma unroll
                    for (int mt = 0; mt < 2; mt++) {
                        uint32_t a[4];
                        a[0] = ph[mt][2 * ktl][0];
                        a[1] = ph[mt][2 * ktl][1];
                        a[2] = ph[mt][2 * ktl + 1][0];
                        a[3] = ph[mt][2 * ktl + 1][1];
                        { uint32_t bb[2] = {b0, b1}; mma_f16(oacc[mt][2 * p],     a, bb); }
                        { uint32_t bb[2] = {b2, b3}; mma_f16(oacc[mt][2 * p + 1], a, bb); }
                    }
                }
            }
        }
    }

    // row sums via quad shuffles; write O (fp16) to g_ao
#pragma unroll
    for (int mt = 0; mt < 2; mt++) {
#pragma unroll
        for (int r = 0; r < 2; r++) {
            lacc[mt][r] += __shfl_xor_sync(0xffffffffu, lacc[mt][r], 1);
            lacc[mt][r] += __shfl_xor_sync(0xffffffffu, lacc[mt][r], 2);
        }
        const float inv0 = 1.f / lacc[mt][0];
        const float inv1 = 1.f / lacc[mt][1];
        __half* obase = g_ao + ((size_t)(b * SEQ + i0 + wid * 32 + mt * 16 + gid)) * DIM + hk;
#pragma unroll
        for (int dt = 0; dt < 8; dt++) {
            const int c = dt * 8 + 2 * tig;
            *reinterpret_cast<uint32_t*>(obase + c) =
                cvt_h2(oacc[mt][dt][0] * inv0, oacc[mt][dt][1] * inv0);
            *reinterpret_cast<uint32_t*>(obase + (size_t)8 * DIM + c) =
                cvt_h2(oacc[mt][dt][2] * inv1, oacc[mt][dt][3] * inv1);
        }
    }
}

// ---------------------------------------------------------------------------
// launch
// ---------------------------------------------------------------------------
extern "C" void kernel_launch(void* const* d_in, const int* in_sizes, int n_in,
                              void* d_out, int out_size)
{
    (void)in_sizes; (void)n_in; (void)out_size;
    const float* q    = (const float*)d_in[0];
    const float* k    = (const float*)d_in[1];
    const float* v    = (const float*)d_in[2];
    const float* bias = (const float*)d_in[3];
    const float* Wq   = (const float*)d_in[4];
    const float* Wk   = (const float*)d_in[5];
    const float* Wv   = (const float*)d_in[6];
    const float* Wo   = (const float*)d_in[7];
    float* out        = (float*)d_out;

    __half *q16, *k16, *v16, *w16, *qh, *kh, *vh, *ao;
    cudaGetSymbolAddress((void**)&q16, g_q16);
    cudaGetSymbolAddress((void**)&k16, g_k16);
    cudaGetSymbolAddress((void**)&v16, g_v16);
    cudaGetSymbolAddress((void**)&w16, g_w16);
    cudaGetSymbolAddress((void**)&qh, g_qh);
    cudaGetSymbolAddress((void**)&kh, g_kh);
    cudaGetSymbolAddress((void**)&vh, g_vh);
    cudaGetSymbolAddress((void**)&ao, g_ao);

    cudaFuncSetAttribute(gemm_h_kernel<__half>,
                         cudaFuncAttributeMaxDynamicSharedMemorySize, GT_SMEM_BYTES);
    cudaFuncSetAttribute(gemm_h_kernel<float>,
                         cudaFuncAttributeMaxDynamicSharedMemorySize, GT_SMEM_BYTES);

    const float scale = 0.125f;  // DHEAD^-0.5
    const int NB = (MTOT * DIM) / 4 / 256;   // 8192
    const int WB = (DIM * DIM) / 4 / 256;    // 1024

    cvt16_qkv_kernel<<<dim3(NB, 3), 256>>>(q, k, v, q16, k16, v16);
    cvt16_w_kernel<<<dim3(WB, 4), 256>>>(Wq, Wk, Wv, Wo, w16);

    dim3 gg(DIM / 256, MTOT / 128);   // (4, 64)
    gemm_h_kernel<__half><<<gg, 512, GT_SMEM_BYTES>>>(q16, w16, qh, scale);
    gemm_h_kernel<__half><<<gg, 512, GT_SMEM_BYTES>>>(k16, w16 + (size_t)DIM * DIM, kh, 1.0f);
    gemm_h_kernel<__half><<<gg, 512, GT_SMEM_BYTES>>>(v16, w16 + (size_t)2 * DIM * DIM, vh, 1.0f);

    // grid.x = (i-block, batch) with batch fastest -> bias L2 reuse across b
    flash_attn_kernel<<<dim3((SEQ / 256) * BATCH, HEADS), 256, 4 * FKV_STG>>>(bias);

    gemm_h_kernel<float><<<gg, 512, GT_SMEM_BYTES>>>(ao, w16 + (size_t)3 * DIM * DIM, out, 1.0f);
}